// round 13
// baseline (speedup 1.0000x reference)
#include <cuda_runtime.h>
#include <cuda_bf16.h>
#include <math.h>
#include <stdint.h>

#define L_SEQ   2048
#define D_MODEL 2048
#define NHEADS  16
#define DHEAD   128
#define DC      512
#define DCQ     1024
#define QHEADS  32

// ---------------------------------------------------------------------------
// Scratch (static device globals -- POD types only; __nv_bfloat16 globals
// break the build (confirmed R8 vs R9))
// ---------------------------------------------------------------------------
__device__ float g_k   [L_SEQ * D_MODEL];
__device__ float g_q   [L_SEQ * 2 * D_MODEL];
__device__ float g_attn[QHEADS * L_SEQ * DHEAD];
__device__ float g_lam [L_SEQ * NHEADS];
__device__ float g_ropecs[L_SEQ * 64 * 2];   // cos/sin table

__device__ unsigned short g_xhi [L_SEQ * D_MODEL],    g_xlo [L_SEQ * D_MODEL];
__device__ unsigned short g_wdkvh[D_MODEL * DC],      g_wdkvl[D_MODEL * DC];
__device__ unsigned short g_wukh [DC * D_MODEL],      g_wukl [DC * D_MODEL];
__device__ unsigned short g_wuvh [DC * D_MODEL],      g_wuvl [DC * D_MODEL];
__device__ unsigned short g_wdqh [D_MODEL * DCQ],     g_wdql [D_MODEL * DCQ];
__device__ unsigned short g_wuqh [DCQ * 2 * D_MODEL], g_wuql [DCQ * 2 * D_MODEL];
__device__ unsigned short g_wouth[D_MODEL * D_MODEL], g_woutl[D_MODEL * D_MODEL];
__device__ unsigned short g_ckvh [L_SEQ * DC],        g_ckvl [L_SEQ * DC];
__device__ unsigned short g_cqh  [L_SEQ * DCQ],       g_cql  [L_SEQ * DCQ];
__device__ unsigned short g_vh   [L_SEQ * D_MODEL],   g_vl   [L_SEQ * D_MODEL];
__device__ unsigned short g_kth  [D_MODEL * L_SEQ],   g_ktl  [D_MODEL * L_SEQ];
__device__ unsigned short g_cmbh [L_SEQ * D_MODEL],   g_cmbl [L_SEQ * D_MODEL];

// ---------------------------------------------------------------------------
// Helpers (sm_80-baseline features only)
// ---------------------------------------------------------------------------
__device__ __forceinline__ uint32_t smem_u32(const void* p) {
    uint32_t r;
    asm("{ .reg .u64 t; cvta.to.shared.u64 t, %1; cvt.u32.u64 %0, t; }"
        : "=r"(r) : "l"(p));
    return r;
}
__device__ __forceinline__ void split_bf(float v, uint16_t& h, uint16_t& l) {
    __nv_bfloat16 hb = __float2bfloat16_rn(v);
    float hf = __bfloat162float(hb);
    __nv_bfloat16 lb = __float2bfloat16_rn(v - hf);
    h = *(uint16_t*)&hb;
    l = *(uint16_t*)&lb;
}
__device__ __forceinline__ void split2(float a, float b, uint32_t& hp, uint32_t& lp) {
    uint16_t ha, la, hb, lb;
    split_bf(a, ha, la);
    split_bf(b, hb, lb);
    hp = (uint32_t)ha | ((uint32_t)hb << 16);
    lp = (uint32_t)la | ((uint32_t)lb << 16);
}
__device__ __forceinline__ void ldsm_x4(uint32_t* r, uint32_t addr) {
    asm volatile("ldmatrix.sync.aligned.m8n8.x4.shared.b16 {%0,%1,%2,%3}, [%4];"
                 : "=r"(r[0]), "=r"(r[1]), "=r"(r[2]), "=r"(r[3]) : "r"(addr));
}
__device__ __forceinline__ void ldsm_x2_t(uint32_t* r, uint32_t addr) {
    asm volatile("ldmatrix.sync.aligned.m8n8.x2.trans.shared.b16 {%0,%1}, [%2];"
                 : "=r"(r[0]), "=r"(r[1]) : "r"(addr));
}
__device__ __forceinline__ void mma_bf16(float* d, const uint32_t* a, const uint32_t* b) {
    asm volatile(
        "mma.sync.aligned.m16n8k16.row.col.f32.bf16.bf16.f32 "
        "{%0,%1,%2,%3}, {%4,%5,%6,%7}, {%8,%9}, {%0,%1,%2,%3};"
        : "+f"(d[0]), "+f"(d[1]), "+f"(d[2]), "+f"(d[3])
        : "r"(a[0]), "r"(a[1]), "r"(a[2]), "r"(a[3]), "r"(b[0]), "r"(b[1]));
}

// ---------------------------------------------------------------------------
// split_kernel: fp32 -> bf16 hi/lo bit-patterns (elementwise)
// ---------------------------------------------------------------------------
__global__ void split_kernel(const float* __restrict__ src,
                             uint16_t* __restrict__ hi, uint16_t* __restrict__ lo)
{
    int i = blockIdx.x * 256 + threadIdx.x;       // float4 index
    float4 v = ((const float4*)src)[i];
    uint32_t h0, l0, h1, l1;
    split2(v.x, v.y, h0, l0);
    split2(v.z, v.w, h1, l1);
    ((uint2*)hi)[i] = make_uint2(h0, h1);
    ((uint2*)lo)[i] = make_uint2(l0, l1);
}

// ---------------------------------------------------------------------------
// ktrans_split: k fp32 [L][2048] -> kT hi/lo [16][128][L]
// ---------------------------------------------------------------------------
__global__ void ktrans_split(const float* __restrict__ k,
                             uint16_t* __restrict__ kth, uint16_t* __restrict__ ktl)
{
    __shared__ float tile[32][33];
    const int l0  = blockIdx.x * 32;
    const int d0  = blockIdx.y * 32;
    const int h   = blockIdx.z;
    const int tx  = threadIdx.x;
    const int ty  = threadIdx.y;

#pragma unroll
    for (int i = 0; i < 4; i++) {
        int lr = ty + i * 8;
        tile[lr][tx] = k[(size_t)(l0 + lr) * D_MODEL + h * DHEAD + d0 + tx];
    }
    __syncthreads();
#pragma unroll
    for (int i = 0; i < 4; i++) {
        int dr = ty + i * 8;
        float v = tile[tx][dr];
        uint16_t hh, ll;
        split_bf(v, hh, ll);
        size_t off = (size_t)(h * DHEAD + d0 + dr) * L_SEQ + l0 + tx;
        kth[off] = hh;
        ktl[off] = ll;
    }
}

// ---------------------------------------------------------------------------
// TC GEMM dual, register-staged pipeline: ldg->regs for it+1 overlaps mma
// of it. Same smem footprint as R11 (37888 B, 2 CTAs/SM possible).
// ---------------------------------------------------------------------------
#define GA_ROW 80
#define GB_ROW 272
#define G_AHI  0
#define G_ALO  (128 * GA_ROW)
#define G_BHI  (2 * 128 * GA_ROW)
#define G_BLO  (G_BHI + 32 * GB_ROW)
#define G_TOT  (G_BLO + 32 * GB_ROW)     // 37888

__device__ __forceinline__ void gemm_ldg(uint4* stg,
    const uint16_t* __restrict__ Ahi, const uint16_t* __restrict__ Alo,
    const uint16_t* __restrict__ Bhi, const uint16_t* __restrict__ Blo,
    int K, int N, int brow, int bcol, int k0, int tid)
{
#pragma unroll
    for (int c = 0; c < 8; c++) {
        int id = c * 256 + tid;
        if (c < 2) {
            int row = id >> 2, c16 = id & 3;
            stg[c] = *(const uint4*)(Ahi + (size_t)(brow + row) * K + k0 + c16 * 8);
        } else if (c < 4) {
            int j = id - 512; int row = j >> 2, c16 = j & 3;
            stg[c] = *(const uint4*)(Alo + (size_t)(brow + row) * K + k0 + c16 * 8);
        } else if (c < 6) {
            int j = id - 1024; int kk = j >> 4, c16 = j & 15;
            stg[c] = *(const uint4*)(Bhi + (size_t)(k0 + kk) * N + bcol + c16 * 8);
        } else {
            int j = id - 1536; int kk = j >> 4, c16 = j & 15;
            stg[c] = *(const uint4*)(Blo + (size_t)(k0 + kk) * N + bcol + c16 * 8);
        }
    }
}
__device__ __forceinline__ void gemm_sts(char* sm, const uint4* stg, int tid)
{
#pragma unroll
    for (int c = 0; c < 8; c++) {
        int id = c * 256 + tid;
        if (c < 2) {
            int row = id >> 2, c16 = id & 3;
            *(uint4*)(sm + G_AHI + row * GA_ROW + c16 * 16) = stg[c];
        } else if (c < 4) {
            int j = id - 512; int row = j >> 2, c16 = j & 3;
            *(uint4*)(sm + G_ALO + row * GA_ROW + c16 * 16) = stg[c];
        } else if (c < 6) {
            int j = id - 1024; int kk = j >> 4, c16 = j & 15;
            *(uint4*)(sm + G_BHI + kk * GB_ROW + c16 * 16) = stg[c];
        } else {
            int j = id - 1536; int kk = j >> 4, c16 = j & 15;
            *(uint4*)(sm + G_BLO + kk * GB_ROW + c16 * 16) = stg[c];
        }
    }
}

__global__ __launch_bounds__(256, 2)
void tc_gemm_dual(const uint16_t* __restrict__ Ahi, const uint16_t* __restrict__ Alo,
                  int K, int nx1,
                  const uint16_t* __restrict__ B1h, const uint16_t* __restrict__ B1l,
                  float* __restrict__ C1f, uint16_t* __restrict__ C1h, uint16_t* __restrict__ C1l,
                  int N1, int mode1,
                  const uint16_t* __restrict__ B2h, const uint16_t* __restrict__ B2l,
                  float* __restrict__ C2f, uint16_t* __restrict__ C2h, uint16_t* __restrict__ C2l,
                  int N2, int mode2)
{
    __shared__ __align__(16) char sm[G_TOT];
    const int tid  = threadIdx.x;
    const int wid  = tid >> 5;
    const int lane = tid & 31;
    const int wr   = wid >> 2;
    const int wc   = wid & 3;
    const int brow = blockIdx.y * 128;

    const uint16_t *Bhi, *Blo;
    float* Cf; uint16_t *Chi, *Clo;
    int N, mode, bcol;
    if ((int)blockIdx.x < nx1) {
        Bhi = B1h; Blo = B1l; Cf = C1f; Chi = C1h; Clo = C1l;
        N = N1; mode = mode1; bcol = blockIdx.x * 128;
    } else {
        Bhi = B2h; Blo = B2l; Cf = C2f; Chi = C2h; Clo = C2l;
        N = N2; mode = mode2; bcol = (blockIdx.x - nx1) * 128;
    }

    const uint32_t sbase = smem_u32(sm);

    float acc[4][4][4];
#pragma unroll
    for (int i = 0; i < 4; i++)
#pragma unroll
        for (int j = 0; j < 4; j++)
#pragma unroll
            for (int t = 0; t < 4; t++) acc[i][j][t] = 0.f;

    const uint32_t a_lane_off = (uint32_t)((lane & 15) * GA_ROW + ((lane >> 4) << 3) * 2);
    const uint32_t b_lane_off = (uint32_t)((lane & 15) * GB_ROW);

    const int nIter = K >> 5;
    uint4 stg[8];
    gemm_ldg(stg, Ahi, Alo, Bhi, Blo, K, N, brow, bcol, 0, tid);

    for (int it = 0; it < nIter; it++) {
        gemm_sts(sm, stg, tid);
        __syncthreads();
        if (it + 1 < nIter)
            gemm_ldg(stg, Ahi, Alo, Bhi, Blo, K, N, brow, bcol, (it + 1) << 5, tid);

#pragma unroll
        for (int ks = 0; ks < 2; ks++) {
            const uint32_t kb16 = (uint32_t)(ks * 16);
            uint32_t bhiF[4][2], bloF[4][2];
#pragma unroll
            for (int fn = 0; fn < 4; fn++) {
                uint32_t nb = (uint32_t)((wc * 32 + fn * 8) * 2);
                uint32_t ba = sbase + kb16 * GB_ROW + b_lane_off + nb;
                ldsm_x2_t(bhiF[fn], ba + G_BHI);
                ldsm_x2_t(bloF[fn], ba + G_BLO);
            }
#pragma unroll
            for (int fm = 0; fm < 4; fm++) {
                uint32_t row0 = (uint32_t)(wr * 64 + fm * 16);
                uint32_t aa = sbase + row0 * GA_ROW + kb16 * 2 + a_lane_off;
                uint32_t ahiF[4], aloF[4];
                ldsm_x4(ahiF, aa + G_AHI);
                ldsm_x4(aloF, aa + G_ALO);
#pragma unroll
                for (int fn = 0; fn < 4; fn++) {
                    mma_bf16(acc[fm][fn], ahiF, bhiF[fn]);
                    mma_bf16(acc[fm][fn], ahiF, bloF[fn]);
                    mma_bf16(acc[fm][fn], aloF, bhiF[fn]);
                }
            }
        }
        __syncthreads();
    }

    if (mode == 0) {
#pragma unroll
        for (int fm = 0; fm < 4; fm++)
#pragma unroll
            for (int fn = 0; fn < 4; fn++) {
                int r0 = brow + wr * 64 + fm * 16 + (lane >> 2);
                int c0 = bcol + wc * 32 + fn * 8 + (lane & 3) * 2;
                *(float2*)&Cf[(size_t)r0 * N + c0] =
                    make_float2(acc[fm][fn][0], acc[fm][fn][1]);
                *(float2*)&Cf[(size_t)(r0 + 8) * N + c0] =
                    make_float2(acc[fm][fn][2], acc[fm][fn][3]);
            }
    } else {
#pragma unroll
        for (int fm = 0; fm < 4; fm++)
#pragma unroll
            for (int fn = 0; fn < 4; fn++) {
                int r0 = brow + wr * 64 + fm * 16 + (lane >> 2);
                int c0 = bcol + wc * 32 + fn * 8 + (lane & 3) * 2;
                uint32_t h0, l0, h1, l1;
                split2(acc[fm][fn][0], acc[fm][fn][1], h0, l0);
                split2(acc[fm][fn][2], acc[fm][fn][3], h1, l1);
                *(uint32_t*)&Chi[(size_t)r0 * N + c0]       = h0;
                *(uint32_t*)&Clo[(size_t)r0 * N + c0]       = l0;
                *(uint32_t*)&Chi[(size_t)(r0 + 8) * N + c0] = h1;
                *(uint32_t*)&Clo[(size_t)(r0 + 8) * N + c0] = l1;
            }
    }
}

// ---------------------------------------------------------------------------
// Tensor-core causal flash attention, register-staged pipeline.
// grid (16 qblocks, 32 qheads), 256 threads. BQ=128, BK=64.
// ---------------------------------------------------------------------------
#define KT_ROW   144
#define V_ROW    272
#define A_KTHI   0
#define A_KTLO   (128 * KT_ROW)                 // 18432
#define A_VHI    (2 * 128 * KT_ROW)             // 36864
#define A_VLO    (A_VHI + 64 * V_ROW)           // 54272
#define ATT_SMEM (A_VLO + 64 * V_ROW)           // 71680

__device__ __forceinline__ void attn_ldg(uint4* stg,
    const uint16_t* __restrict__ kth, const uint16_t* __restrict__ ktl,
    const uint16_t* __restrict__ vh, const uint16_t* __restrict__ vl,
    int kvh, int kb, int tid)
{
#pragma unroll
    for (int c = 0; c < 16; c++) {
        int id = c * 256 + tid;
        if (c < 4) {
            int dh = id >> 3, kc = id & 7;
            stg[c] = *(const uint4*)(kth + (size_t)(kvh * DHEAD + dh) * L_SEQ + kb * 64 + kc * 8);
        } else if (c < 8) {
            int j = id - 1024; int dh = j >> 3, kc = j & 7;
            stg[c] = *(const uint4*)(ktl + (size_t)(kvh * DHEAD + dh) * L_SEQ + kb * 64 + kc * 8);
        } else if (c < 12) {
            int j = id - 2048; int key = j >> 4, c16 = j & 15;
            stg[c] = *(const uint4*)(vh + (size_t)(kb * 64 + key) * D_MODEL + kvh * DHEAD + c16 * 8);
        } else {
            int j = id - 3072; int key = j >> 4, c16 = j & 15;
            stg[c] = *(const uint4*)(vl + (size_t)(kb * 64 + key) * D_MODEL + kvh * DHEAD + c16 * 8);
        }
    }
}
__device__ __forceinline__ void attn_sts(char* sm, const uint4* stg, int tid)
{
#pragma unroll
    for (int c = 0; c < 16; c++) {
        int id = c * 256 + tid;
        if (c < 4) {
            int dh = id >> 3, kc = id & 7;
            *(uint4*)(sm + A_KTHI + dh * KT_ROW + kc * 16) = stg[c];
        } else if (c < 8) {
            int j = id - 1024; int dh = j >> 3, kc = j & 7;
            *(uint4*)(sm + A_KTLO + dh * KT_ROW + kc * 16) = stg[c];
        } else if (c < 12) {
            int j = id - 2048; int key = j >> 4, c16 = j & 15;
            *(uint4*)(sm + A_VHI + key * V_ROW + c16 * 16) = stg[c];
        } else {
            int j = id - 3072; int key = j >> 4, c16 = j & 15;
            *(uint4*)(sm + A_VLO + key * V_ROW + c16 * 16) = stg[c];
        }
    }
}

__global__ __launch_bounds__(256, 1) void attn_tc3(
    const float* __restrict__ q,
    const uint16_t* __restrict__ kth, const uint16_t* __restrict__ ktl,
    const uint16_t* __restrict__ vh,  const uint16_t* __restrict__ vl,
    float* __restrict__ o)
{
    extern __shared__ char sm[];
    const int qb   = blockIdx.x;
    const int qh   = blockIdx.y;
    const int kvh  = qh >> 1;
    const int tid  = threadIdx.x;
    const int w    = tid >> 5;
    const int lane = tid & 31;
    const uint32_t sbase = smem_u32(sm);
    const float scale = 0.08838834764831843f;

    uint32_t qhi[8][4], qlo[8][4];
    {
        const int r0 = qb * 128 + w * 16 + (lane >> 2);
        const float* q0 = q + (size_t)r0 * 4096 + qh * 128 + (lane & 3) * 2;
        const float* q1 = q0 + 8 * 4096;
#pragma unroll
        for (int kf = 0; kf < 8; kf++) {
            float2 x0 = *(const float2*)(q0 + kf * 16);
            float2 x1 = *(const float2*)(q1 + kf * 16);
            float2 x2 = *(const float2*)(q0 + kf * 16 + 8);
            float2 x3 = *(const float2*)(q1 + kf * 16 + 8);
            split2(x0.x * scale, x0.y * scale, qhi[kf][0], qlo[kf][0]);
            split2(x1.x * scale, x1.y * scale, qhi[kf][1], qlo[kf][1]);
            split2(x2.x * scale, x2.y * scale, qhi[kf][2], qlo[kf][2]);
            split2(x3.x * scale, x3.y * scale, qhi[kf][3], qlo[kf][3]);
        }
    }

    float m0 = -1e30f, m1 = -1e30f, l0 = 0.f, l1 = 0.f;
    float O[16][4];
#pragma unroll
    for (int d = 0; d < 16; d++)
#pragma unroll
        for (int t = 0; t < 4; t++) O[d][t] = 0.f;

    const int kb_max = 2 * qb + 1;
    uint4 stg[16];
    attn_ldg(stg, kth, ktl, vh, vl, kvh, 0, tid);

    for (int kb = 0; kb <= kb_max; kb++) {
        attn_sts(sm, stg, tid);
        __syncthreads();
        if (kb < kb_max)
            attn_ldg(stg, kth, ktl, vh, vl, kvh, kb + 1, tid);

        float s[8][4];
#pragma unroll
        for (int j = 0; j < 8; j++) {
            s[j][0] = s[j][1] = s[j][2] = s[j][3] = 0.f;
#pragma unroll
            for (int kf = 0; kf < 8; kf++) {
                uint32_t addr = sbase + (uint32_t)((kf * 16 + (lane & 15)) * KT_ROW + j * 16);
                uint32_t bh[2], bl[2];
                ldsm_x2_t(bh, addr + A_KTHI);
                ldsm_x2_t(bl, addr + A_KTLO);
                mma_bf16(s[j], qhi[kf], bh);
                mma_bf16(s[j], qhi[kf], bl);
                mma_bf16(s[j], qlo[kf], bh);
            }
        }

        if (kb >= 2 * qb) {
            int row0 = qb * 128 + w * 16 + (lane >> 2);
            int colb = kb * 64 + (lane & 3) * 2;
#pragma unroll
            for (int j = 0; j < 8; j++) {
                int c0 = colb + j * 8;
                if (c0     > row0)     s[j][0] = -1e30f;
                if (c0 + 1 > row0)     s[j][1] = -1e30f;
                if (c0     > row0 + 8) s[j][2] = -1e30f;
                if (c0 + 1 > row0 + 8) s[j][3] = -1e30f;
            }
        }

        float mx0 = -1e30f, mx1 = -1e30f;
#pragma unroll
        for (int j = 0; j < 8; j++) {
            mx0 = fmaxf(mx0, fmaxf(s[j][0], s[j][1]));
            mx1 = fmaxf(mx1, fmaxf(s[j][2], s[j][3]));
        }
        mx0 = fmaxf(mx0, __shfl_xor_sync(0xffffffffu, mx0, 1));
        mx0 = fmaxf(mx0, __shfl_xor_sync(0xffffffffu, mx0, 2));
        mx1 = fmaxf(mx1, __shfl_xor_sync(0xffffffffu, mx1, 1));
        mx1 = fmaxf(mx1, __shfl_xor_sync(0xffffffffu, mx1, 2));
        float mn0 = fmaxf(m0, mx0), mn1 = fmaxf(m1, mx1);
        float a0 = __expf(m0 - mn0), a1 = __expf(m1 - mn1);
        m0 = mn0; m1 = mn1;
        float rs0 = 0.f, rs1 = 0.f;
#pragma unroll
        for (int j = 0; j < 8; j++) {
            s[j][0] = __expf(s[j][0] - mn0);
            s[j][1] = __expf(s[j][1] - mn0);
            s[j][2] = __expf(s[j][2] - mn1);
            s[j][3] = __expf(s[j][3] - mn1);
            rs0 += s[j][0] + s[j][1];
            rs1 += s[j][2] + s[j][3];
        }
        rs0 += __shfl_xor_sync(0xffffffffu, rs0, 1);
        rs0 += __shfl_xor_sync(0xffffffffu, rs0, 2);
        rs1 += __shfl_xor_sync(0xffffffffu, rs1, 1);
        rs1 += __shfl_xor_sync(0xffffffffu, rs1, 2);
        l0 = l0 * a0 + rs0;
        l1 = l1 * a1 + rs1;
#pragma unroll
        for (int d = 0; d < 16; d++) {
            O[d][0] *= a0; O[d][1] *= a0;
            O[d][2] *= a1; O[d][3] *= a1;
        }

        uint32_t phi[4][4], plo[4][4];
#pragma unroll
        for (int kf2 = 0; kf2 < 4; kf2++) {
            split2(s[2 * kf2][0],     s[2 * kf2][1],     phi[kf2][0], plo[kf2][0]);
            split2(s[2 * kf2][2],     s[2 * kf2][3],     phi[kf2][1], plo[kf2][1]);
            split2(s[2 * kf2 + 1][0], s[2 * kf2 + 1][1], phi[kf2][2], plo[kf2][2]);
            split2(s[2 * kf2 + 1][2], s[2 * kf2 + 1][3], phi[kf2][3], plo[kf2][3]);
        }

#pragma unroll
        for (int d = 0; d < 16; d++) {
#pragma unroll
            for (int kf2 = 0; kf2 < 4; kf2++) {
                uint32_t addr = sbase + (uint32_t)((kf2 * 16 + (lane & 15)) * V_ROW + d * 16);
                uint32_t bh[2], bl[2];
                ldsm_x2_t(bh, addr + A_VHI);
                ldsm_x2_t(bl, addr + A_VLO);
                mma_bf16(O[d], phi[kf2], bh);
                mma_bf16(O[d], phi[kf2], bl);
                mma_bf16(O[d], plo[kf2], bh);
            }
        }
        __syncthreads();
    }

    float i0 = 1.f / l0, i1 = 1.f / l1;
    int r0 = qb * 128 + w * 16 + (lane >> 2);
#pragma unroll
    for (int d = 0; d < 16; d++) {
        int col = d * 8 + (lane & 3) * 2;
        *(float2*)&o[((size_t)qh * L_SEQ + r0) * 128 + col] =
            make_float2(O[d][0] * i0, O[d][1] * i0);
        *(float2*)&o[((size_t)qh * L_SEQ + r0 + 8) * 128 + col] =
            make_float2(O[d][2] * i1, O[d][3] * i1);
    }
}

// ---------------------------------------------------------------------------
// RoPE: table build + bandwidth-only apply
// ---------------------------------------------------------------------------
__global__ void rope_table_kernel()
{
    int i = blockIdx.x * 256 + threadIdx.x;       // 0 .. 131071
    int l = i >> 6, d = i & 63;
    float inv_freq = exp2f(-(float)d * (13.287712379549449f / 64.f));
    float s, c;
    sincosf((float)l * inv_freq, &s, &c);
    g_ropecs[i * 2]     = c;
    g_ropecs[i * 2 + 1] = s;
}

__global__ void rope_kernel(float* __restrict__ buf, int stride)
{
    const int l = blockIdx.x;
    const int h = blockIdx.y;
    const int d = threadIdx.x;

    float2 cs = *(const float2*)&g_ropecs[(l * 64 + d) * 2];

    float* p = buf + (size_t)l * stride + h * DHEAD;
    float x1 = p[d];
    float x2 = p[d + 64];
    p[d]      = x1 * cs.x - x2 * cs.y;
    p[d + 64] = x2 * cs.x + x1 * cs.y;
}

// ---------------------------------------------------------------------------
// lam = sigmoid(x @ W_lam + b_lam)
// ---------------------------------------------------------------------------
__global__ void lam_kernel(const float* __restrict__ x,
                           const float* __restrict__ Wl,
                           const float* __restrict__ bl,
                           float* __restrict__ lam)
{
    __shared__ float part[256];
    const int l = blockIdx.x;
    const int t = threadIdx.x;
    const int h = t & 15;
    const int p = t >> 4;

    float s = 0.f;
#pragma unroll 4
    for (int j = 0; j < 128; j++) {
        int kk = p * 128 + j;
        s += x[(size_t)l * D_MODEL + kk] * Wl[(size_t)kk * NHEADS + h];
    }
    part[t] = s;
    __syncthreads();
    if (t < NHEADS) {
        float tot = bl[t];
#pragma unroll
        for (int p2 = 0; p2 < 16; p2++) tot += part[p2 * 16 + t];
        lam[(size_t)l * NHEADS + t] = 1.f / (1.f + __expf(-tot));
    }
}

// ---------------------------------------------------------------------------
// combine: emits bf16 hi/lo bit patterns directly for the Wout GEMM
// ---------------------------------------------------------------------------
__global__ void combine_kernel2(const float* __restrict__ attn,
                                const float* __restrict__ lam,
                                uint16_t* __restrict__ hi, uint16_t* __restrict__ lo)
{
    int idx = blockIdx.x * 256 + threadIdx.x;     // over L*1024 pairs
    int l  = idx >> 10;
    int cp = idx & 1023;
    int h  = cp >> 6;
    int dp = (cp & 63) * 2;
    float a1a = attn[((size_t)(2 * h)     * L_SEQ + l) * DHEAD + dp];
    float a1b = attn[((size_t)(2 * h)     * L_SEQ + l) * DHEAD + dp + 1];
    float a2a = attn[((size_t)(2 * h + 1) * L_SEQ + l) * DHEAD + dp];
    float a2b = attn[((size_t)(2 * h + 1) * L_SEQ + l) * DHEAD + dp + 1];
    float lm  = lam[(size_t)l * NHEADS + h];
    uint32_t hw, lw;
    split2(a1a - lm * a2a, a1b - lm * a2b, hw, lw);
    ((uint32_t*)hi)[idx] = hw;
    ((uint32_t*)lo)[idx] = lw;
}

// ---------------------------------------------------------------------------
// kernel_launch
// inputs: 0=x 1=W_DKV 2=W_UK 3=W_UV 4=W_DQ 5=W_UQ 6=W_lam 7=b_lam 8=W_out
// ---------------------------------------------------------------------------
extern "C" void kernel_launch(void* const* d_in, const int* in_sizes, int n_in,
                              void* d_out, int out_size)
{
    const float* x     = (const float*)d_in[0];
    const float* W_DKV = (const float*)d_in[1];
    const float* W_UK  = (const float*)d_in[2];
    const float* W_UV  = (const float*)d_in[3];
    const float* W_DQ  = (const float*)d_in[4];
    const float* W_UQ  = (const float*)d_in[5];
    const float* W_lam = (const float*)d_in[6];
    const float* b_lam = (const float*)d_in[7];
    const float* W_out = (const float*)d_in[8];
    float* out = (float*)d_out;

    float *kbuf, *qbuf, *attn, *lam;
    cudaGetSymbolAddress((void**)&kbuf, g_k);
    cudaGetSymbolAddress((void**)&qbuf, g_q);
    cudaGetSymbolAddress((void**)&attn, g_attn);
    cudaGetSymbolAddress((void**)&lam,  g_lam);

    uint16_t *xh,*xl,*wdkvh,*wdkvl,*wukh,*wukl,*wuvh,*wuvl,*wdqh,*wdql,
             *wuqh,*wuql,*wouth,*woutl,*ckvh,*ckvl,*cqh,*cql,*vh,*vl,
             *kth,*ktl,*cmbh,*cmbl;
    cudaGetSymbolAddress((void**)&xh,    g_xhi);   cudaGetSymbolAddress((void**)&xl,    g_xlo);
    cudaGetSymbolAddress((void**)&wdkvh, g_wdkvh); cudaGetSymbolAddress((void**)&wdkvl, g_wdkvl);
    cudaGetSymbolAddress((void**)&wukh,  g_wukh);  cudaGetSymbolAddress((void**)&wukl,  g_wukl);
    cudaGetSymbolAddress((void**)&wuvh,  g_wuvh);  cudaGetSymbolAddress((void**)&wuvl,  g_wuvl);
    cudaGetSymbolAddress((void**)&wdqh,  g_wdqh);  cudaGetSymbolAddress((void**)&wdql,  g_wdql);
    cudaGetSymbolAddress((void**)&wuqh,  g_wuqh);  cudaGetSymbolAddress((void**)&wuql,  g_wuql);
    cudaGetSymbolAddress((void**)&wouth, g_wouth); cudaGetSymbolAddress((void**)&woutl, g_woutl);
    cudaGetSymbolAddress((void**)&ckvh,  g_ckvh);  cudaGetSymbolAddress((void**)&ckvl,  g_ckvl);
    cudaGetSymbolAddress((void**)&cqh,   g_cqh);   cudaGetSymbolAddress((void**)&cql,   g_cql);
    cudaGetSymbolAddress((void**)&vh,    g_vh);    cudaGetSymbolAddress((void**)&vl,    g_vl);
    cudaGetSymbolAddress((void**)&kth,   g_kth);   cudaGetSymbolAddress((void**)&ktl,   g_ktl);
    cudaGetSymbolAddress((void**)&cmbh,  g_cmbh);  cudaGetSymbolAddress((void**)&cmbl,  g_cmbl);

    cudaFuncSetAttribute(attn_tc3, cudaFuncAttributeMaxDynamicSharedMemorySize, ATT_SMEM);

    // rope table + pre-split inputs (elementwise)
    rope_table_kernel<<<512, 256>>>();
    split_kernel<<<(L_SEQ * D_MODEL) / 1024, 256>>>(x,     xh,    xl);
    split_kernel<<<(D_MODEL * DC) / 1024,    256>>>(W_DKV, wdkvh, wdkvl);
    split_kernel<<<(DC * D_MODEL) / 1024,    256>>>(W_UK,  wukh,  wukl);
    split_kernel<<<(DC * D_MODEL) / 1024,    256>>>(W_UV,  wuvh,  wuvl);
    split_kernel<<<(D_MODEL * DCQ) / 1024,   256>>>(W_DQ,  wdqh,  wdql);
    split_kernel<<<(DCQ * 2 * D_MODEL)/1024, 256>>>(W_UQ,  wuqh,  wuql);
    split_kernel<<<(D_MODEL * D_MODEL)/1024, 256>>>(W_out, wouth, woutl);

    // fused DKV || DQ  (both read x, K=2048): grid (4+8, 16) = 192 CTAs
    tc_gemm_dual<<<dim3(4 + 8, 16), 256>>>(xh, xl, D_MODEL, 4,
        wdkvh, wdkvl, nullptr, ckvh, ckvl, DC,  1,
        wdqh,  wdql,  nullptr, cqh,  cql,  DCQ, 1);

    // fused UK || UV  (both read ckv, K=512): grid (16+16, 16) = 512 CTAs
    tc_gemm_dual<<<dim3(16 + 16, 16), 256>>>(ckvh, ckvl, DC, 16,
        wukh, wukl, kbuf,    nullptr, nullptr, D_MODEL, 0,
        wuvh, wuvl, nullptr, vh,      vl,      D_MODEL, 1);

    // UQ (512 CTAs)
    tc_gemm_dual<<<dim3(32, 16), 256>>>(cqh, cql, DCQ, 32,
        wuqh, wuql, qbuf, nullptr, nullptr, 2 * D_MODEL, 0,
        wuqh, wuql, qbuf, nullptr, nullptr, 2 * D_MODEL, 0);

    // RoPE (table-driven)
    rope_kernel<<<dim3(L_SEQ, QHEADS), 64>>>(qbuf, 2 * D_MODEL);
    rope_kernel<<<dim3(L_SEQ, NHEADS), 64>>>(kbuf, D_MODEL);

    // K -> transposed hi/lo
    ktrans_split<<<dim3(L_SEQ / 32, 4, NHEADS), dim3(32, 8)>>>(kbuf, kth, ktl);

    // gate
    lam_kernel<<<L_SEQ, 256>>>(x, W_lam, b_lam, lam);

    // attention
    attn_tc3<<<dim3(L_SEQ / 128, QHEADS), 256, ATT_SMEM>>>(qbuf, kth, ktl, vh, vl, attn);

    // differential combine -> bf16 hi/lo
    combine_kernel2<<<(L_SEQ * D_MODEL / 2) / 256, 256>>>(attn, lam, cmbh, cmbl);

    // output projection
    tc_gemm_dual<<<dim3(16, 16), 256>>>(cmbh, cmbl, D_MODEL, 16,
        wouth, woutl, out, nullptr, nullptr, D_MODEL, 0,
        wouth, woutl, out, nullptr, nullptr, D_MODEL, 0);
}

// round 15
// speedup vs baseline: 1.1531x; 1.1531x over previous
#include <cuda_runtime.h>
#include <cuda_bf16.h>
#include <math.h>
#include <stdint.h>

#define L_SEQ   2048
#define D_MODEL 2048
#define NHEADS  16
#define DHEAD   128
#define DC      512
#define DCQ     1024
#define QHEADS  32

// ---------------------------------------------------------------------------
// Scratch (static device globals -- POD types only; __nv_bfloat16 globals
// break the build (confirmed R8 vs R9))
// ---------------------------------------------------------------------------
__device__ float g_k   [L_SEQ * D_MODEL];
__device__ float g_q   [L_SEQ * 2 * D_MODEL];
__device__ float g_attn[QHEADS * L_SEQ * DHEAD];
__device__ float g_lam [L_SEQ * NHEADS];
__device__ float g_ropecs[L_SEQ * 64 * 2];   // cos/sin table

__device__ unsigned short g_xhi [L_SEQ * D_MODEL],    g_xlo [L_SEQ * D_MODEL];
__device__ unsigned short g_wdkvh[D_MODEL * DC],      g_wdkvl[D_MODEL * DC];
__device__ unsigned short g_wukh [DC * D_MODEL],      g_wukl [DC * D_MODEL];
__device__ unsigned short g_wuvh [DC * D_MODEL],      g_wuvl [DC * D_MODEL];
__device__ unsigned short g_wdqh [D_MODEL * DCQ],     g_wdql [D_MODEL * DCQ];
__device__ unsigned short g_wuqh [DCQ * 2 * D_MODEL], g_wuql [DCQ * 2 * D_MODEL];
__device__ unsigned short g_wouth[D_MODEL * D_MODEL], g_woutl[D_MODEL * D_MODEL];
__device__ unsigned short g_ckvh [L_SEQ * DC],        g_ckvl [L_SEQ * DC];
__device__ unsigned short g_cqh  [L_SEQ * DCQ],       g_cql  [L_SEQ * DCQ];
__device__ unsigned short g_vh   [L_SEQ * D_MODEL],   g_vl   [L_SEQ * D_MODEL];
__device__ unsigned short g_kth  [D_MODEL * L_SEQ],   g_ktl  [D_MODEL * L_SEQ];
__device__ unsigned short g_cmbh [L_SEQ * D_MODEL],   g_cmbl [L_SEQ * D_MODEL];

// ---------------------------------------------------------------------------
// Helpers (sm_80-baseline features only)
// ---------------------------------------------------------------------------
__device__ __forceinline__ uint32_t smem_u32(const void* p) {
    uint32_t r;
    asm("{ .reg .u64 t; cvta.to.shared.u64 t, %1; cvt.u32.u64 %0, t; }"
        : "=r"(r) : "l"(p));
    return r;
}
__device__ __forceinline__ void split_bf(float v, uint16_t& h, uint16_t& l) {
    __nv_bfloat16 hb = __float2bfloat16_rn(v);
    float hf = __bfloat162float(hb);
    __nv_bfloat16 lb = __float2bfloat16_rn(v - hf);
    h = *(uint16_t*)&hb;
    l = *(uint16_t*)&lb;
}
__device__ __forceinline__ void split2(float a, float b, uint32_t& hp, uint32_t& lp) {
    uint16_t ha, la, hb, lb;
    split_bf(a, ha, la);
    split_bf(b, hb, lb);
    hp = (uint32_t)ha | ((uint32_t)hb << 16);
    lp = (uint32_t)la | ((uint32_t)lb << 16);
}
__device__ __forceinline__ void ldsm_x4(uint32_t* r, uint32_t addr) {
    asm volatile("ldmatrix.sync.aligned.m8n8.x4.shared.b16 {%0,%1,%2,%3}, [%4];"
                 : "=r"(r[0]), "=r"(r[1]), "=r"(r[2]), "=r"(r[3]) : "r"(addr));
}
__device__ __forceinline__ void ldsm_x2_t(uint32_t* r, uint32_t addr) {
    asm volatile("ldmatrix.sync.aligned.m8n8.x2.trans.shared.b16 {%0,%1}, [%2];"
                 : "=r"(r[0]), "=r"(r[1]) : "r"(addr));
}
__device__ __forceinline__ void mma_bf16(float* d, const uint32_t* a, const uint32_t* b) {
    asm volatile(
        "mma.sync.aligned.m16n8k16.row.col.f32.bf16.bf16.f32 "
        "{%0,%1,%2,%3}, {%4,%5,%6,%7}, {%8,%9}, {%0,%1,%2,%3};"
        : "+f"(d[0]), "+f"(d[1]), "+f"(d[2]), "+f"(d[3])
        : "r"(a[0]), "r"(a[1]), "r"(a[2]), "r"(a[3]), "r"(b[0]), "r"(b[1]));
}

// ---------------------------------------------------------------------------
// split_kernel: fp32 -> bf16 hi/lo bit-patterns (elementwise)
// ---------------------------------------------------------------------------
__global__ void split_kernel(const float* __restrict__ src,
                             uint16_t* __restrict__ hi, uint16_t* __restrict__ lo)
{
    int i = blockIdx.x * 256 + threadIdx.x;       // float4 index
    float4 v = ((const float4*)src)[i];
    uint32_t h0, l0, h1, l1;
    split2(v.x, v.y, h0, l0);
    split2(v.z, v.w, h1, l1);
    ((uint2*)hi)[i] = make_uint2(h0, h1);
    ((uint2*)lo)[i] = make_uint2(l0, l1);
}

// ---------------------------------------------------------------------------
// ktrans_split: k fp32 [L][2048] -> kT hi/lo [16][128][L]
// ---------------------------------------------------------------------------
__global__ void ktrans_split(const float* __restrict__ k,
                             uint16_t* __restrict__ kth, uint16_t* __restrict__ ktl)
{
    __shared__ float tile[32][33];
    const int l0  = blockIdx.x * 32;
    const int d0  = blockIdx.y * 32;
    const int h   = blockIdx.z;
    const int tx  = threadIdx.x;
    const int ty  = threadIdx.y;

#pragma unroll
    for (int i = 0; i < 4; i++) {
        int lr = ty + i * 8;
        tile[lr][tx] = k[(size_t)(l0 + lr) * D_MODEL + h * DHEAD + d0 + tx];
    }
    __syncthreads();
#pragma unroll
    for (int i = 0; i < 4; i++) {
        int dr = ty + i * 8;
        float v = tile[tx][dr];
        uint16_t hh, ll;
        split_bf(v, hh, ll);
        size_t off = (size_t)(h * DHEAD + d0 + dr) * L_SEQ + l0 + tx;
        kth[off] = hh;
        ktl[off] = ll;
    }
}

// ---------------------------------------------------------------------------
// TC GEMM dual (R11 synchronous version -- best measured). One launch can
// serve TWO independent GEMMs sharing A and K (block-routed by blockIdx.x).
// ---------------------------------------------------------------------------
#define GA_ROW 80
#define GB_ROW 272
#define G_AHI  0
#define G_ALO  (128 * GA_ROW)
#define G_BHI  (2 * 128 * GA_ROW)
#define G_BLO  (G_BHI + 32 * GB_ROW)
#define G_TOT  (G_BLO + 32 * GB_ROW)     // 37888

__global__ __launch_bounds__(256, 2)
void tc_gemm_dual(const uint16_t* __restrict__ Ahi, const uint16_t* __restrict__ Alo,
                  int K, int nx1,
                  const uint16_t* __restrict__ B1h, const uint16_t* __restrict__ B1l,
                  float* __restrict__ C1f, uint16_t* __restrict__ C1h, uint16_t* __restrict__ C1l,
                  int N1, int mode1,
                  const uint16_t* __restrict__ B2h, const uint16_t* __restrict__ B2l,
                  float* __restrict__ C2f, uint16_t* __restrict__ C2h, uint16_t* __restrict__ C2l,
                  int N2, int mode2)
{
    __shared__ __align__(16) char sm[G_TOT];
    const int tid  = threadIdx.x;
    const int wid  = tid >> 5;
    const int lane = tid & 31;
    const int wr   = wid >> 2;
    const int wc   = wid & 3;
    const int brow = blockIdx.y * 128;

    const uint16_t *Bhi, *Blo;
    float* Cf; uint16_t *Chi, *Clo;
    int N, mode, bcol;
    if ((int)blockIdx.x < nx1) {
        Bhi = B1h; Blo = B1l; Cf = C1f; Chi = C1h; Clo = C1l;
        N = N1; mode = mode1; bcol = blockIdx.x * 128;
    } else {
        Bhi = B2h; Blo = B2l; Cf = C2f; Chi = C2h; Clo = C2l;
        N = N2; mode = mode2; bcol = (blockIdx.x - nx1) * 128;
    }

    const uint32_t sbase = smem_u32(sm);

    float acc[4][4][4];
#pragma unroll
    for (int i = 0; i < 4; i++)
#pragma unroll
        for (int j = 0; j < 4; j++)
#pragma unroll
            for (int t = 0; t < 4; t++) acc[i][j][t] = 0.f;

    const uint32_t a_lane_off = (uint32_t)((lane & 15) * GA_ROW + ((lane >> 4) << 3) * 2);
    const uint32_t b_lane_off = (uint32_t)((lane & 15) * GB_ROW);

    const int nIter = K >> 5;
    for (int it = 0; it < nIter; it++) {
        const int k0 = it << 5;
#pragma unroll
        for (int c = 0; c < 8; c++) {
            int id = c * 256 + tid;
            if (c < 2) {
                int row = id >> 2, c16 = id & 3;
                uint4 v = *(const uint4*)(Ahi + (size_t)(brow + row) * K + k0 + c16 * 8);
                *(uint4*)(sm + G_AHI + row * GA_ROW + c16 * 16) = v;
            } else if (c < 4) {
                int j = id - 512;
                int row = j >> 2, c16 = j & 3;
                uint4 v = *(const uint4*)(Alo + (size_t)(brow + row) * K + k0 + c16 * 8);
                *(uint4*)(sm + G_ALO + row * GA_ROW + c16 * 16) = v;
            } else if (c < 6) {
                int j = id - 1024;
                int kk = j >> 4, c16 = j & 15;
                uint4 v = *(const uint4*)(Bhi + (size_t)(k0 + kk) * N + bcol + c16 * 8);
                *(uint4*)(sm + G_BHI + kk * GB_ROW + c16 * 16) = v;
            } else {
                int j = id - 1536;
                int kk = j >> 4, c16 = j & 15;
                uint4 v = *(const uint4*)(Blo + (size_t)(k0 + kk) * N + bcol + c16 * 8);
                *(uint4*)(sm + G_BLO + kk * GB_ROW + c16 * 16) = v;
            }
        }
        __syncthreads();

#pragma unroll
        for (int ks = 0; ks < 2; ks++) {
            const uint32_t kb16 = (uint32_t)(ks * 16);
            uint32_t bhiF[4][2], bloF[4][2];
#pragma unroll
            for (int fn = 0; fn < 4; fn++) {
                uint32_t nb = (uint32_t)((wc * 32 + fn * 8) * 2);
                uint32_t ba = sbase + kb16 * GB_ROW + b_lane_off + nb;
                ldsm_x2_t(bhiF[fn], ba + G_BHI);
                ldsm_x2_t(bloF[fn], ba + G_BLO);
            }
#pragma unroll
            for (int fm = 0; fm < 4; fm++) {
                uint32_t row0 = (uint32_t)(wr * 64 + fm * 16);
                uint32_t aa = sbase + row0 * GA_ROW + kb16 * 2 + a_lane_off;
                uint32_t ahiF[4], aloF[4];
                ldsm_x4(ahiF, aa + G_AHI);
                ldsm_x4(aloF, aa + G_ALO);
#pragma unroll
                for (int fn = 0; fn < 4; fn++) {
                    mma_bf16(acc[fm][fn], ahiF, bhiF[fn]);
                    mma_bf16(acc[fm][fn], ahiF, bloF[fn]);
                    mma_bf16(acc[fm][fn], aloF, bhiF[fn]);
                }
            }
        }
        __syncthreads();
    }

    if (mode == 0) {
#pragma unroll
        for (int fm = 0; fm < 4; fm++)
#pragma unroll
            for (int fn = 0; fn < 4; fn++) {
                int r0 = brow + wr * 64 + fm * 16 + (lane >> 2);
                int c0 = bcol + wc * 32 + fn * 8 + (lane & 3) * 2;
                *(float2*)&Cf[(size_t)r0 * N + c0] =
                    make_float2(acc[fm][fn][0], acc[fm][fn][1]);
                *(float2*)&Cf[(size_t)(r0 + 8) * N + c0] =
                    make_float2(acc[fm][fn][2], acc[fm][fn][3]);
            }
    } else {
#pragma unroll
        for (int fm = 0; fm < 4; fm++)
#pragma unroll
            for (int fn = 0; fn < 4; fn++) {
                int r0 = brow + wr * 64 + fm * 16 + (lane >> 2);
                int c0 = bcol + wc * 32 + fn * 8 + (lane & 3) * 2;
                uint32_t h0, l0, h1, l1;
                split2(acc[fm][fn][0], acc[fm][fn][1], h0, l0);
                split2(acc[fm][fn][2], acc[fm][fn][3], h1, l1);
                *(uint32_t*)&Chi[(size_t)r0 * N + c0]       = h0;
                *(uint32_t*)&Clo[(size_t)r0 * N + c0]       = l0;
                *(uint32_t*)&Chi[(size_t)(r0 + 8) * N + c0] = h1;
                *(uint32_t*)&Clo[(size_t)(r0 + 8) * N + c0] = l1;
            }
    }
}

// ---------------------------------------------------------------------------
// Tensor-core causal flash attention (R11 synchronous version) with
// heavy-first CTA ordering: qb = gridDim.x-1-blockIdx.x so the 32-iteration
// blocks launch in wave 1 instead of forming the tail.
// ---------------------------------------------------------------------------
#define KT_ROW   144
#define V_ROW    272
#define A_KTHI   0
#define A_KTLO   (128 * KT_ROW)                 // 18432
#define A_VHI    (2 * 128 * KT_ROW)             // 36864
#define A_VLO    (A_VHI + 64 * V_ROW)           // 54272
#define ATT_SMEM (A_VLO + 64 * V_ROW)           // 71680

__global__ __launch_bounds__(256, 1) void attn_tc3(
    const float* __restrict__ q,
    const uint16_t* __restrict__ kth, const uint16_t* __restrict__ ktl,
    const uint16_t* __restrict__ vh,  const uint16_t* __restrict__ vl,
    float* __restrict__ o)
{
    extern __shared__ char sm[];
    const int qb   = gridDim.x - 1 - blockIdx.x;   // heavy blocks first
    const int qh   = blockIdx.y;
    const int kvh  = qh >> 1;
    const int tid  = threadIdx.x;
    const int w    = tid >> 5;
    const int lane = tid & 31;
    const uint32_t sbase = smem_u32(sm);
    const float scale = 0.08838834764831843f;

    uint32_t qhi[8][4], qlo[8][4];
    {
        const int r0 = qb * 128 + w * 16 + (lane >> 2);
        const float* q0 = q + (size_t)r0 * 4096 + qh * 128 + (lane & 3) * 2;
        const float* q1 = q0 + 8 * 4096;
#pragma unroll
        for (int kf = 0; kf < 8; kf++) {
            float2 x0 = *(const float2*)(q0 + kf * 16);
            float2 x1 = *(const float2*)(q1 + kf * 16);
            float2 x2 = *(const float2*)(q0 + kf * 16 + 8);
            float2 x3 = *(const float2*)(q1 + kf * 16 + 8);
            split2(x0.x * scale, x0.y * scale, qhi[kf][0], qlo[kf][0]);
            split2(x1.x * scale, x1.y * scale, qhi[kf][1], qlo[kf][1]);
            split2(x2.x * scale, x2.y * scale, qhi[kf][2], qlo[kf][2]);
            split2(x3.x * scale, x3.y * scale, qhi[kf][3], qlo[kf][3]);
        }
    }

    float m0 = -1e30f, m1 = -1e30f, l0 = 0.f, l1 = 0.f;
    float O[16][4];
#pragma unroll
    for (int d = 0; d < 16; d++)
#pragma unroll
        for (int t = 0; t < 4; t++) O[d][t] = 0.f;

    const int kb_max = 2 * qb + 1;
    for (int kb = 0; kb <= kb_max; kb++) {
        __syncthreads();

#pragma unroll
        for (int c = 0; c < 16; c++) {
            int id = c * 256 + tid;
            if (c < 4) {
                int dh = id >> 3, kc = id & 7;
                uint4 v = *(const uint4*)(kth + (size_t)(kvh * DHEAD + dh) * L_SEQ + kb * 64 + kc * 8);
                *(uint4*)(sm + A_KTHI + dh * KT_ROW + kc * 16) = v;
            } else if (c < 8) {
                int j = id - 1024;
                int dh = j >> 3, kc = j & 7;
                uint4 v = *(const uint4*)(ktl + (size_t)(kvh * DHEAD + dh) * L_SEQ + kb * 64 + kc * 8);
                *(uint4*)(sm + A_KTLO + dh * KT_ROW + kc * 16) = v;
            } else if (c < 12) {
                int j = id - 2048;
                int key = j >> 4, c16 = j & 15;
                uint4 v = *(const uint4*)(vh + (size_t)(kb * 64 + key) * D_MODEL + kvh * DHEAD + c16 * 8);
                *(uint4*)(sm + A_VHI + key * V_ROW + c16 * 16) = v;
            } else {
                int j = id - 3072;
                int key = j >> 4, c16 = j & 15;
                uint4 v = *(const uint4*)(vl + (size_t)(kb * 64 + key) * D_MODEL + kvh * DHEAD + c16 * 8);
                *(uint4*)(sm + A_VLO + key * V_ROW + c16 * 16) = v;
            }
        }
        __syncthreads();

        float s[8][4];
#pragma unroll
        for (int j = 0; j < 8; j++) {
            s[j][0] = s[j][1] = s[j][2] = s[j][3] = 0.f;
#pragma unroll
            for (int kf = 0; kf < 8; kf++) {
                uint32_t addr = sbase + (uint32_t)((kf * 16 + (lane & 15)) * KT_ROW + j * 16);
                uint32_t bh[2], bl[2];
                ldsm_x2_t(bh, addr + A_KTHI);
                ldsm_x2_t(bl, addr + A_KTLO);
                mma_bf16(s[j], qhi[kf], bh);
                mma_bf16(s[j], qhi[kf], bl);
                mma_bf16(s[j], qlo[kf], bh);
            }
        }

        if (kb >= 2 * qb) {
            int row0 = qb * 128 + w * 16 + (lane >> 2);
            int colb = kb * 64 + (lane & 3) * 2;
#pragma unroll
            for (int j = 0; j < 8; j++) {
                int c0 = colb + j * 8;
                if (c0     > row0)     s[j][0] = -1e30f;
                if (c0 + 1 > row0)     s[j][1] = -1e30f;
                if (c0     > row0 + 8) s[j][2] = -1e30f;
                if (c0 + 1 > row0 + 8) s[j][3] = -1e30f;
            }
        }

        float mx0 = -1e30f, mx1 = -1e30f;
#pragma unroll
        for (int j = 0; j < 8; j++) {
            mx0 = fmaxf(mx0, fmaxf(s[j][0], s[j][1]));
            mx1 = fmaxf(mx1, fmaxf(s[j][2], s[j][3]));
        }
        mx0 = fmaxf(mx0, __shfl_xor_sync(0xffffffffu, mx0, 1));
        mx0 = fmaxf(mx0, __shfl_xor_sync(0xffffffffu, mx0, 2));
        mx1 = fmaxf(mx1, __shfl_xor_sync(0xffffffffu, mx1, 1));
        mx1 = fmaxf(mx1, __shfl_xor_sync(0xffffffffu, mx1, 2));
        float mn0 = fmaxf(m0, mx0), mn1 = fmaxf(m1, mx1);
        float a0 = __expf(m0 - mn0), a1 = __expf(m1 - mn1);
        m0 = mn0; m1 = mn1;
        float rs0 = 0.f, rs1 = 0.f;
#pragma unroll
        for (int j = 0; j < 8; j++) {
            s[j][0] = __expf(s[j][0] - mn0);
            s[j][1] = __expf(s[j][1] - mn0);
            s[j][2] = __expf(s[j][2] - mn1);
            s[j][3] = __expf(s[j][3] - mn1);
            rs0 += s[j][0] + s[j][1];
            rs1 += s[j][2] + s[j][3];
        }
        rs0 += __shfl_xor_sync(0xffffffffu, rs0, 1);
        rs0 += __shfl_xor_sync(0xffffffffu, rs0, 2);
        rs1 += __shfl_xor_sync(0xffffffffu, rs1, 1);
        rs1 += __shfl_xor_sync(0xffffffffu, rs1, 2);
        l0 = l0 * a0 + rs0;
        l1 = l1 * a1 + rs1;
#pragma unroll
        for (int d = 0; d < 16; d++) {
            O[d][0] *= a0; O[d][1] *= a0;
            O[d][2] *= a1; O[d][3] *= a1;
        }

        uint32_t phi[4][4], plo[4][4];
#pragma unroll
        for (int kf2 = 0; kf2 < 4; kf2++) {
            split2(s[2 * kf2][0],     s[2 * kf2][1],     phi[kf2][0], plo[kf2][0]);
            split2(s[2 * kf2][2],     s[2 * kf2][3],     phi[kf2][1], plo[kf2][1]);
            split2(s[2 * kf2 + 1][0], s[2 * kf2 + 1][1], phi[kf2][2], plo[kf2][2]);
            split2(s[2 * kf2 + 1][2], s[2 * kf2 + 1][3], phi[kf2][3], plo[kf2][3]);
        }

#pragma unroll
        for (int d = 0; d < 16; d++) {
#pragma unroll
            for (int kf2 = 0; kf2 < 4; kf2++) {
                uint32_t addr = sbase + (uint32_t)((kf2 * 16 + (lane & 15)) * V_ROW + d * 16);
                uint32_t bh[2], bl[2];
                ldsm_x2_t(bh, addr + A_VHI);
                ldsm_x2_t(bl, addr + A_VLO);
                mma_bf16(O[d], phi[kf2], bh);
                mma_bf16(O[d], phi[kf2], bl);
                mma_bf16(O[d], plo[kf2], bh);
            }
        }
    }

    float i0 = 1.f / l0, i1 = 1.f / l1;
    int r0 = qb * 128 + w * 16 + (lane >> 2);
#pragma unroll
    for (int d = 0; d < 16; d++) {
        int col = d * 8 + (lane & 3) * 2;
        *(float2*)&o[((size_t)qh * L_SEQ + r0) * 128 + col] =
            make_float2(O[d][0] * i0, O[d][1] * i0);
        *(float2*)&o[((size_t)qh * L_SEQ + r0 + 8) * 128 + col] =
            make_float2(O[d][2] * i1, O[d][3] * i1);
    }
}

// ---------------------------------------------------------------------------
// RoPE: table build + bandwidth-only apply
// ---------------------------------------------------------------------------
__global__ void rope_table_kernel()
{
    int i = blockIdx.x * 256 + threadIdx.x;       // 0 .. 131071
    int l = i >> 6, d = i & 63;
    float inv_freq = exp2f(-(float)d * (13.287712379549449f / 64.f));
    float s, c;
    sincosf((float)l * inv_freq, &s, &c);
    g_ropecs[i * 2]     = c;
    g_ropecs[i * 2 + 1] = s;
}

__global__ void rope_kernel(float* __restrict__ buf, int stride)
{
    const int l = blockIdx.x;
    const int h = blockIdx.y;
    const int d = threadIdx.x;

    float2 cs = *(const float2*)&g_ropecs[(l * 64 + d) * 2];

    float* p = buf + (size_t)l * stride + h * DHEAD;
    float x1 = p[d];
    float x2 = p[d + 64];
    p[d]      = x1 * cs.x - x2 * cs.y;
    p[d + 64] = x2 * cs.x + x1 * cs.y;
}

// ---------------------------------------------------------------------------
// lam = sigmoid(x @ W_lam + b_lam)
// ---------------------------------------------------------------------------
__global__ void lam_kernel(const float* __restrict__ x,
                           const float* __restrict__ Wl,
                           const float* __restrict__ bl,
                           float* __restrict__ lam)
{
    __shared__ float part[256];
    const int l = blockIdx.x;
    const int t = threadIdx.x;
    const int h = t & 15;
    const int p = t >> 4;

    float s = 0.f;
#pragma unroll 4
    for (int j = 0; j < 128; j++) {
        int kk = p * 128 + j;
        s += x[(size_t)l * D_MODEL + kk] * Wl[(size_t)kk * NHEADS + h];
    }
    part[t] = s;
    __syncthreads();
    if (t < NHEADS) {
        float tot = bl[t];
#pragma unroll
        for (int p2 = 0; p2 < 16; p2++) tot += part[p2 * 16 + t];
        lam[(size_t)l * NHEADS + t] = 1.f / (1.f + __expf(-tot));
    }
}

// ---------------------------------------------------------------------------
// combine: emits bf16 hi/lo bit patterns directly for the Wout GEMM
// ---------------------------------------------------------------------------
__global__ void combine_kernel2(const float* __restrict__ attn,
                                const float* __restrict__ lam,
                                uint16_t* __restrict__ hi, uint16_t* __restrict__ lo)
{
    int idx = blockIdx.x * 256 + threadIdx.x;     // over L*1024 pairs
    int l  = idx >> 10;
    int cp = idx & 1023;
    int h  = cp >> 6;
    int dp = (cp & 63) * 2;
    float a1a = attn[((size_t)(2 * h)     * L_SEQ + l) * DHEAD + dp];
    float a1b = attn[((size_t)(2 * h)     * L_SEQ + l) * DHEAD + dp + 1];
    float a2a = attn[((size_t)(2 * h + 1) * L_SEQ + l) * DHEAD + dp];
    float a2b = attn[((size_t)(2 * h + 1) * L_SEQ + l) * DHEAD + dp + 1];
    float lm  = lam[(size_t)l * NHEADS + h];
    uint32_t hw, lw;
    split2(a1a - lm * a2a, a1b - lm * a2b, hw, lw);
    ((uint32_t*)hi)[idx] = hw;
    ((uint32_t*)lo)[idx] = lw;
}

// ---------------------------------------------------------------------------
// kernel_launch
// inputs: 0=x 1=W_DKV 2=W_UK 3=W_UV 4=W_DQ 5=W_UQ 6=W_lam 7=b_lam 8=W_out
// ---------------------------------------------------------------------------
extern "C" void kernel_launch(void* const* d_in, const int* in_sizes, int n_in,
                              void* d_out, int out_size)
{
    const float* x     = (const float*)d_in[0];
    const float* W_DKV = (const float*)d_in[1];
    const float* W_UK  = (const float*)d_in[2];
    const float* W_UV  = (const float*)d_in[3];
    const float* W_DQ  = (const float*)d_in[4];
    const float* W_UQ  = (const float*)d_in[5];
    const float* W_lam = (const float*)d_in[6];
    const float* b_lam = (const float*)d_in[7];
    const float* W_out = (const float*)d_in[8];
    float* out = (float*)d_out;

    float *kbuf, *qbuf, *attn, *lam;
    cudaGetSymbolAddress((void**)&kbuf, g_k);
    cudaGetSymbolAddress((void**)&qbuf, g_q);
    cudaGetSymbolAddress((void**)&attn, g_attn);
    cudaGetSymbolAddress((void**)&lam,  g_lam);

    uint16_t *xh,*xl,*wdkvh,*wdkvl,*wukh,*wukl,*wuvh,*wuvl,*wdqh,*wdql,
             *wuqh,*wuql,*wouth,*woutl,*ckvh,*ckvl,*cqh,*cql,*vh,*vl,
             *kth,*ktl,*cmbh,*cmbl;
    cudaGetSymbolAddress((void**)&xh,    g_xhi);   cudaGetSymbolAddress((void**)&xl,    g_xlo);
    cudaGetSymbolAddress((void**)&wdkvh, g_wdkvh); cudaGetSymbolAddress((void**)&wdkvl, g_wdkvl);
    cudaGetSymbolAddress((void**)&wukh,  g_wukh);  cudaGetSymbolAddress((void**)&wukl,  g_wukl);
    cudaGetSymbolAddress((void**)&wuvh,  g_wuvh);  cudaGetSymbolAddress((void**)&wuvl,  g_wuvl);
    cudaGetSymbolAddress((void**)&wdqh,  g_wdqh);  cudaGetSymbolAddress((void**)&wdql,  g_wdql);
    cudaGetSymbolAddress((void**)&wuqh,  g_wuqh);  cudaGetSymbolAddress((void**)&wuql,  g_wuql);
    cudaGetSymbolAddress((void**)&wouth, g_wouth); cudaGetSymbolAddress((void**)&woutl, g_woutl);
    cudaGetSymbolAddress((void**)&ckvh,  g_ckvh);  cudaGetSymbolAddress((void**)&ckvl,  g_ckvl);
    cudaGetSymbolAddress((void**)&cqh,   g_cqh);   cudaGetSymbolAddress((void**)&cql,   g_cql);
    cudaGetSymbolAddress((void**)&vh,    g_vh);    cudaGetSymbolAddress((void**)&vl,    g_vl);
    cudaGetSymbolAddress((void**)&kth,   g_kth);   cudaGetSymbolAddress((void**)&ktl,   g_ktl);
    cudaGetSymbolAddress((void**)&cmbh,  g_cmbh);  cudaGetSymbolAddress((void**)&cmbl,  g_cmbl);

    cudaFuncSetAttribute(attn_tc3, cudaFuncAttributeMaxDynamicSharedMemorySize, ATT_SMEM);

    // rope table + pre-split inputs (elementwise)
    rope_table_kernel<<<512, 256>>>();
    split_kernel<<<(L_SEQ * D_MODEL) / 1024, 256>>>(x,     xh,    xl);
    split_kernel<<<(D_MODEL * DC) / 1024,    256>>>(W_DKV, wdkvh, wdkvl);
    split_kernel<<<(DC * D_MODEL) / 1024,    256>>>(W_UK,  wukh,  wukl);
    split_kernel<<<(DC * D_MODEL) / 1024,    256>>>(W_UV,  wuvh,  wuvl);
    split_kernel<<<(D_MODEL * DCQ) / 1024,   256>>>(W_DQ,  wdqh,  wdql);
    split_kernel<<<(DCQ * 2 * D_MODEL)/1024, 256>>>(W_UQ,  wuqh,  wuql);
    split_kernel<<<(D_MODEL * D_MODEL)/1024, 256>>>(W_out, wouth, woutl);

    // fused DKV || DQ  (both read x, K=2048): grid (4+8, 16) = 192 CTAs
    tc_gemm_dual<<<dim3(4 + 8, 16), 256>>>(xh, xl, D_MODEL, 4,
        wdkvh, wdkvl, nullptr, ckvh, ckvl, DC,  1,
        wdqh,  wdql,  nullptr, cqh,  cql,  DCQ, 1);

    // fused UK || UV  (both read ckv, K=512): grid (16+16, 16) = 512 CTAs
    tc_gemm_dual<<<dim3(16 + 16, 16), 256>>>(ckvh, ckvl, DC, 16,
        wukh, wukl, kbuf,    nullptr, nullptr, D_MODEL, 0,
        wuvh, wuvl, nullptr, vh,      vl,      D_MODEL, 1);

    // UQ (512 CTAs)
    tc_gemm_dual<<<dim3(32, 16), 256>>>(cqh, cql, DCQ, 32,
        wuqh, wuql, qbuf, nullptr, nullptr, 2 * D_MODEL, 0,
        wuqh, wuql, qbuf, nullptr, nullptr, 2 * D_MODEL, 0);

    // RoPE (table-driven)
    rope_kernel<<<dim3(L_SEQ, QHEADS), 64>>>(qbuf, 2 * D_MODEL);
    rope_kernel<<<dim3(L_SEQ, NHEADS), 64>>>(kbuf, D_MODEL);

    // K -> transposed hi/lo
    ktrans_split<<<dim3(L_SEQ / 32, 4, NHEADS), dim3(32, 8)>>>(kbuf, kth, ktl);

    // gate
    lam_kernel<<<L_SEQ, 256>>>(x, W_lam, b_lam, lam);

    // attention (heavy-first ordering)
    attn_tc3<<<dim3(L_SEQ / 128, QHEADS), 256, ATT_SMEM>>>(qbuf, kth, ktl, vh, vl, attn);

    // differential combine -> bf16 hi/lo
    combine_kernel2<<<(L_SEQ * D_MODEL / 2) / 256, 256>>>(attn, lam, cmbh, cmbl);

    // output projection
    tc_gemm_dual<<<dim3(16, 16), 256>>>(cmbh, cmbl, D_MODEL, 16,
        wouth, woutl, out, nullptr, nullptr, D_MODEL, 0,
        wouth, woutl, out, nullptr, nullptr, D_MODEL, 0);
}

// round 16
// speedup vs baseline: 1.1735x; 1.0177x over previous
#include <cuda_runtime.h>
#include <cuda_bf16.h>
#include <math.h>
#include <stdint.h>

#define L_SEQ   2048
#define D_MODEL 2048
#define NHEADS  16
#define DHEAD   128
#define DC      512
#define DCQ     1024
#define QHEADS  32

// ---------------------------------------------------------------------------
// Scratch (static device globals -- POD types only; __nv_bfloat16 globals
// break the build (confirmed R8 vs R9))
// ---------------------------------------------------------------------------
__device__ float g_k   [L_SEQ * D_MODEL];
__device__ float g_q   [L_SEQ * 2 * D_MODEL];
__device__ float g_attn[QHEADS * L_SEQ * DHEAD];
__device__ float g_lam [L_SEQ * NHEADS];
__device__ float g_ropecs[L_SEQ * 64 * 2];   // cos/sin table

__device__ unsigned short g_xhi [L_SEQ * D_MODEL],    g_xlo [L_SEQ * D_MODEL];
__device__ unsigned short g_wdkvh[D_MODEL * DC],      g_wdkvl[D_MODEL * DC];
__device__ unsigned short g_wukh [DC * D_MODEL],      g_wukl [DC * D_MODEL];
__device__ unsigned short g_wuvh [DC * D_MODEL],      g_wuvl [DC * D_MODEL];
__device__ unsigned short g_wdqh [D_MODEL * DCQ],     g_wdql [D_MODEL * DCQ];
__device__ unsigned short g_wuqh [DCQ * 2 * D_MODEL], g_wuql [DCQ * 2 * D_MODEL];
__device__ unsigned short g_wouth[D_MODEL * D_MODEL], g_woutl[D_MODEL * D_MODEL];
__device__ unsigned short g_ckvh [L_SEQ * DC],        g_ckvl [L_SEQ * DC];
__device__ unsigned short g_cqh  [L_SEQ * DCQ],       g_cql  [L_SEQ * DCQ];
__device__ unsigned short g_vh   [L_SEQ * D_MODEL],   g_vl   [L_SEQ * D_MODEL];
__device__ unsigned short g_kth  [D_MODEL * L_SEQ],   g_ktl  [D_MODEL * L_SEQ];
__device__ unsigned short g_cmbh [L_SEQ * D_MODEL],   g_cmbl [L_SEQ * D_MODEL];

// ---------------------------------------------------------------------------
// Helpers (sm_80-baseline features only)
// ---------------------------------------------------------------------------
__device__ __forceinline__ uint32_t smem_u32(const void* p) {
    uint32_t r;
    asm("{ .reg .u64 t; cvta.to.shared.u64 t, %1; cvt.u32.u64 %0, t; }"
        : "=r"(r) : "l"(p));
    return r;
}
__device__ __forceinline__ void split_bf(float v, uint16_t& h, uint16_t& l) {
    __nv_bfloat16 hb = __float2bfloat16_rn(v);
    float hf = __bfloat162float(hb);
    __nv_bfloat16 lb = __float2bfloat16_rn(v - hf);
    h = *(uint16_t*)&hb;
    l = *(uint16_t*)&lb;
}
__device__ __forceinline__ void split2(float a, float b, uint32_t& hp, uint32_t& lp) {
    uint16_t ha, la, hb, lb;
    split_bf(a, ha, la);
    split_bf(b, hb, lb);
    hp = (uint32_t)ha | ((uint32_t)hb << 16);
    lp = (uint32_t)la | ((uint32_t)lb << 16);
}
__device__ __forceinline__ void ldsm_x4(uint32_t* r, uint32_t addr) {
    asm volatile("ldmatrix.sync.aligned.m8n8.x4.shared.b16 {%0,%1,%2,%3}, [%4];"
                 : "=r"(r[0]), "=r"(r[1]), "=r"(r[2]), "=r"(r[3]) : "r"(addr));
}
__device__ __forceinline__ void ldsm_x2_t(uint32_t* r, uint32_t addr) {
    asm volatile("ldmatrix.sync.aligned.m8n8.x2.trans.shared.b16 {%0,%1}, [%2];"
                 : "=r"(r[0]), "=r"(r[1]) : "r"(addr));
}
__device__ __forceinline__ void mma_bf16(float* d, const uint32_t* a, const uint32_t* b) {
    asm volatile(
        "mma.sync.aligned.m16n8k16.row.col.f32.bf16.bf16.f32 "
        "{%0,%1,%2,%3}, {%4,%5,%6,%7}, {%8,%9}, {%0,%1,%2,%3};"
        : "+f"(d[0]), "+f"(d[1]), "+f"(d[2]), "+f"(d[3])
        : "r"(a[0]), "r"(a[1]), "r"(a[2]), "r"(a[3]), "r"(b[0]), "r"(b[1]));
}

// ---------------------------------------------------------------------------
// split_kernel: fp32 -> bf16 hi/lo bit-patterns (elementwise)
// ---------------------------------------------------------------------------
__global__ void split_kernel(const float* __restrict__ src,
                             uint16_t* __restrict__ hi, uint16_t* __restrict__ lo)
{
    int i = blockIdx.x * 256 + threadIdx.x;       // float4 index
    float4 v = ((const float4*)src)[i];
    uint32_t h0, l0, h1, l1;
    split2(v.x, v.y, h0, l0);
    split2(v.z, v.w, h1, l1);
    ((uint2*)hi)[i] = make_uint2(h0, h1);
    ((uint2*)lo)[i] = make_uint2(l0, l1);
}

// ---------------------------------------------------------------------------
// ktrans_split: k fp32 [L][2048] -> kT hi/lo [16][128][L]
// ---------------------------------------------------------------------------
__global__ void ktrans_split(const float* __restrict__ k,
                             uint16_t* __restrict__ kth, uint16_t* __restrict__ ktl)
{
    __shared__ float tile[32][33];
    const int l0  = blockIdx.x * 32;
    const int d0  = blockIdx.y * 32;
    const int h   = blockIdx.z;
    const int tx  = threadIdx.x;
    const int ty  = threadIdx.y;

#pragma unroll
    for (int i = 0; i < 4; i++) {
        int lr = ty + i * 8;
        tile[lr][tx] = k[(size_t)(l0 + lr) * D_MODEL + h * DHEAD + d0 + tx];
    }
    __syncthreads();
#pragma unroll
    for (int i = 0; i < 4; i++) {
        int dr = ty + i * 8;
        float v = tile[tx][dr];
        uint16_t hh, ll;
        split_bf(v, hh, ll);
        size_t off = (size_t)(h * DHEAD + d0 + dr) * L_SEQ + l0 + tx;
        kth[off] = hh;
        ktl[off] = ll;
    }
}

// ---------------------------------------------------------------------------
// TC GEMM multi-job: proven synchronous inner loop; up to 3 independent
// GEMMs per launch, block-routed by blockIdx.x (heavy job first).
// ---------------------------------------------------------------------------
struct GemmJob {
    const uint16_t *Ah, *Al, *Bh, *Bl;
    float* Cf;
    uint16_t *Ch, *Cl;
    int K, N, nx, mode;   // nx = number of 128-col tiles; mode 0 fp32, 1 hi/lo
};

#define GA_ROW 80
#define GB_ROW 272
#define G_AHI  0
#define G_ALO  (128 * GA_ROW)
#define G_BHI  (2 * 128 * GA_ROW)
#define G_BLO  (G_BHI + 32 * GB_ROW)
#define G_TOT  (G_BLO + 32 * GB_ROW)     // 37888

__global__ __launch_bounds__(256, 2)
void tc_gemm_multi(GemmJob j0, GemmJob j1, GemmJob j2)
{
    __shared__ __align__(16) char sm[G_TOT];
    const int tid  = threadIdx.x;
    const int wid  = tid >> 5;
    const int lane = tid & 31;
    const int wr   = wid >> 2;
    const int wc   = wid & 3;
    const int brow = blockIdx.y * 128;

    // uniform per-block routing
    GemmJob j;
    int bx = blockIdx.x;
    if (bx < j0.nx)                { j = j0; }
    else if (bx < j0.nx + j1.nx)   { j = j1; bx -= j0.nx; }
    else                           { j = j2; bx -= j0.nx + j1.nx; }
    const int bcol = bx * 128;
    const int K = j.K, N = j.N;

    const uint32_t sbase = smem_u32(sm);

    float acc[4][4][4];
#pragma unroll
    for (int i = 0; i < 4; i++)
#pragma unroll
        for (int jj = 0; jj < 4; jj++)
#pragma unroll
            for (int t = 0; t < 4; t++) acc[i][jj][t] = 0.f;

    const uint32_t a_lane_off = (uint32_t)((lane & 15) * GA_ROW + ((lane >> 4) << 3) * 2);
    const uint32_t b_lane_off = (uint32_t)((lane & 15) * GB_ROW);

    const int nIter = K >> 5;
    for (int it = 0; it < nIter; it++) {
        const int k0 = it << 5;
#pragma unroll
        for (int c = 0; c < 8; c++) {
            int id = c * 256 + tid;
            if (c < 2) {
                int row = id >> 2, c16 = id & 3;
                uint4 v = *(const uint4*)(j.Ah + (size_t)(brow + row) * K + k0 + c16 * 8);
                *(uint4*)(sm + G_AHI + row * GA_ROW + c16 * 16) = v;
            } else if (c < 4) {
                int jx = id - 512;
                int row = jx >> 2, c16 = jx & 3;
                uint4 v = *(const uint4*)(j.Al + (size_t)(brow + row) * K + k0 + c16 * 8);
                *(uint4*)(sm + G_ALO + row * GA_ROW + c16 * 16) = v;
            } else if (c < 6) {
                int jx = id - 1024;
                int kk = jx >> 4, c16 = jx & 15;
                uint4 v = *(const uint4*)(j.Bh + (size_t)(k0 + kk) * N + bcol + c16 * 8);
                *(uint4*)(sm + G_BHI + kk * GB_ROW + c16 * 16) = v;
            } else {
                int jx = id - 1536;
                int kk = jx >> 4, c16 = jx & 15;
                uint4 v = *(const uint4*)(j.Bl + (size_t)(k0 + kk) * N + bcol + c16 * 8);
                *(uint4*)(sm + G_BLO + kk * GB_ROW + c16 * 16) = v;
            }
        }
        __syncthreads();

#pragma unroll
        for (int ks = 0; ks < 2; ks++) {
            const uint32_t kb16 = (uint32_t)(ks * 16);
            uint32_t bhiF[4][2], bloF[4][2];
#pragma unroll
            for (int fn = 0; fn < 4; fn++) {
                uint32_t nb = (uint32_t)((wc * 32 + fn * 8) * 2);
                uint32_t ba = sbase + kb16 * GB_ROW + b_lane_off + nb;
                ldsm_x2_t(bhiF[fn], ba + G_BHI);
                ldsm_x2_t(bloF[fn], ba + G_BLO);
            }
#pragma unroll
            for (int fm = 0; fm < 4; fm++) {
                uint32_t row0 = (uint32_t)(wr * 64 + fm * 16);
                uint32_t aa = sbase + row0 * GA_ROW + kb16 * 2 + a_lane_off;
                uint32_t ahiF[4], aloF[4];
                ldsm_x4(ahiF, aa + G_AHI);
                ldsm_x4(aloF, aa + G_ALO);
#pragma unroll
                for (int fn = 0; fn < 4; fn++) {
                    mma_bf16(acc[fm][fn], ahiF, bhiF[fn]);
                    mma_bf16(acc[fm][fn], ahiF, bloF[fn]);
                    mma_bf16(acc[fm][fn], aloF, bhiF[fn]);
                }
            }
        }
        __syncthreads();
    }

    if (j.mode == 0) {
#pragma unroll
        for (int fm = 0; fm < 4; fm++)
#pragma unroll
            for (int fn = 0; fn < 4; fn++) {
                int r0 = brow + wr * 64 + fm * 16 + (lane >> 2);
                int c0 = bcol + wc * 32 + fn * 8 + (lane & 3) * 2;
                *(float2*)&j.Cf[(size_t)r0 * N + c0] =
                    make_float2(acc[fm][fn][0], acc[fm][fn][1]);
                *(float2*)&j.Cf[(size_t)(r0 + 8) * N + c0] =
                    make_float2(acc[fm][fn][2], acc[fm][fn][3]);
            }
    } else {
#pragma unroll
        for (int fm = 0; fm < 4; fm++)
#pragma unroll
            for (int fn = 0; fn < 4; fn++) {
                int r0 = brow + wr * 64 + fm * 16 + (lane >> 2);
                int c0 = bcol + wc * 32 + fn * 8 + (lane & 3) * 2;
                uint32_t h0, l0, h1, l1;
                split2(acc[fm][fn][0], acc[fm][fn][1], h0, l0);
                split2(acc[fm][fn][2], acc[fm][fn][3], h1, l1);
                *(uint32_t*)&j.Ch[(size_t)r0 * N + c0]       = h0;
                *(uint32_t*)&j.Cl[(size_t)r0 * N + c0]       = l0;
                *(uint32_t*)&j.Ch[(size_t)(r0 + 8) * N + c0] = h1;
                *(uint32_t*)&j.Cl[(size_t)(r0 + 8) * N + c0] = l1;
            }
    }
}

// ---------------------------------------------------------------------------
// Tensor-core causal flash attention (R14 version, heavy-first ordering)
// ---------------------------------------------------------------------------
#define KT_ROW   144
#define V_ROW    272
#define A_KTHI   0
#define A_KTLO   (128 * KT_ROW)                 // 18432
#define A_VHI    (2 * 128 * KT_ROW)             // 36864
#define A_VLO    (A_VHI + 64 * V_ROW)           // 54272
#define ATT_SMEM (A_VLO + 64 * V_ROW)           // 71680

__global__ __launch_bounds__(256, 1) void attn_tc3(
    const float* __restrict__ q,
    const uint16_t* __restrict__ kth, const uint16_t* __restrict__ ktl,
    const uint16_t* __restrict__ vh,  const uint16_t* __restrict__ vl,
    float* __restrict__ o)
{
    extern __shared__ char sm[];
    const int qb   = gridDim.x - 1 - blockIdx.x;   // heavy blocks first
    const int qh   = blockIdx.y;
    const int kvh  = qh >> 1;
    const int tid  = threadIdx.x;
    const int w    = tid >> 5;
    const int lane = tid & 31;
    const uint32_t sbase = smem_u32(sm);
    const float scale = 0.08838834764831843f;

    uint32_t qhi[8][4], qlo[8][4];
    {
        const int r0 = qb * 128 + w * 16 + (lane >> 2);
        const float* q0 = q + (size_t)r0 * 4096 + qh * 128 + (lane & 3) * 2;
        const float* q1 = q0 + 8 * 4096;
#pragma unroll
        for (int kf = 0; kf < 8; kf++) {
            float2 x0 = *(const float2*)(q0 + kf * 16);
            float2 x1 = *(const float2*)(q1 + kf * 16);
            float2 x2 = *(const float2*)(q0 + kf * 16 + 8);
            float2 x3 = *(const float2*)(q1 + kf * 16 + 8);
            split2(x0.x * scale, x0.y * scale, qhi[kf][0], qlo[kf][0]);
            split2(x1.x * scale, x1.y * scale, qhi[kf][1], qlo[kf][1]);
            split2(x2.x * scale, x2.y * scale, qhi[kf][2], qlo[kf][2]);
            split2(x3.x * scale, x3.y * scale, qhi[kf][3], qlo[kf][3]);
        }
    }

    float m0 = -1e30f, m1 = -1e30f, l0 = 0.f, l1 = 0.f;
    float O[16][4];
#pragma unroll
    for (int d = 0; d < 16; d++)
#pragma unroll
        for (int t = 0; t < 4; t++) O[d][t] = 0.f;

    const int kb_max = 2 * qb + 1;
    for (int kb = 0; kb <= kb_max; kb++) {
        __syncthreads();

#pragma unroll
        for (int c = 0; c < 16; c++) {
            int id = c * 256 + tid;
            if (c < 4) {
                int dh = id >> 3, kc = id & 7;
                uint4 v = *(const uint4*)(kth + (size_t)(kvh * DHEAD + dh) * L_SEQ + kb * 64 + kc * 8);
                *(uint4*)(sm + A_KTHI + dh * KT_ROW + kc * 16) = v;
            } else if (c < 8) {
                int j = id - 1024;
                int dh = j >> 3, kc = j & 7;
                uint4 v = *(const uint4*)(ktl + (size_t)(kvh * DHEAD + dh) * L_SEQ + kb * 64 + kc * 8);
                *(uint4*)(sm + A_KTLO + dh * KT_ROW + kc * 16) = v;
            } else if (c < 12) {
                int j = id - 2048;
                int key = j >> 4, c16 = j & 15;
                uint4 v = *(const uint4*)(vh + (size_t)(kb * 64 + key) * D_MODEL + kvh * DHEAD + c16 * 8);
                *(uint4*)(sm + A_VHI + key * V_ROW + c16 * 16) = v;
            } else {
                int j = id - 3072;
                int key = j >> 4, c16 = j & 15;
                uint4 v = *(const uint4*)(vl + (size_t)(kb * 64 + key) * D_MODEL + kvh * DHEAD + c16 * 8);
                *(uint4*)(sm + A_VLO + key * V_ROW + c16 * 16) = v;
            }
        }
        __syncthreads();

        float s[8][4];
#pragma unroll
        for (int j = 0; j < 8; j++) {
            s[j][0] = s[j][1] = s[j][2] = s[j][3] = 0.f;
#pragma unroll
            for (int kf = 0; kf < 8; kf++) {
                uint32_t addr = sbase + (uint32_t)((kf * 16 + (lane & 15)) * KT_ROW + j * 16);
                uint32_t bh[2], bl[2];
                ldsm_x2_t(bh, addr + A_KTHI);
                ldsm_x2_t(bl, addr + A_KTLO);
                mma_bf16(s[j], qhi[kf], bh);
                mma_bf16(s[j], qhi[kf], bl);
                mma_bf16(s[j], qlo[kf], bh);
            }
        }

        if (kb >= 2 * qb) {
            int row0 = qb * 128 + w * 16 + (lane >> 2);
            int colb = kb * 64 + (lane & 3) * 2;
#pragma unroll
            for (int j = 0; j < 8; j++) {
                int c0 = colb + j * 8;
                if (c0     > row0)     s[j][0] = -1e30f;
                if (c0 + 1 > row0)     s[j][1] = -1e30f;
                if (c0     > row0 + 8) s[j][2] = -1e30f;
                if (c0 + 1 > row0 + 8) s[j][3] = -1e30f;
            }
        }

        float mx0 = -1e30f, mx1 = -1e30f;
#pragma unroll
        for (int j = 0; j < 8; j++) {
            mx0 = fmaxf(mx0, fmaxf(s[j][0], s[j][1]));
            mx1 = fmaxf(mx1, fmaxf(s[j][2], s[j][3]));
        }
        mx0 = fmaxf(mx0, __shfl_xor_sync(0xffffffffu, mx0, 1));
        mx0 = fmaxf(mx0, __shfl_xor_sync(0xffffffffu, mx0, 2));
        mx1 = fmaxf(mx1, __shfl_xor_sync(0xffffffffu, mx1, 1));
        mx1 = fmaxf(mx1, __shfl_xor_sync(0xffffffffu, mx1, 2));
        float mn0 = fmaxf(m0, mx0), mn1 = fmaxf(m1, mx1);
        float a0 = __expf(m0 - mn0), a1 = __expf(m1 - mn1);
        m0 = mn0; m1 = mn1;
        float rs0 = 0.f, rs1 = 0.f;
#pragma unroll
        for (int j = 0; j < 8; j++) {
            s[j][0] = __expf(s[j][0] - mn0);
            s[j][1] = __expf(s[j][1] - mn0);
            s[j][2] = __expf(s[j][2] - mn1);
            s[j][3] = __expf(s[j][3] - mn1);
            rs0 += s[j][0] + s[j][1];
            rs1 += s[j][2] + s[j][3];
        }
        rs0 += __shfl_xor_sync(0xffffffffu, rs0, 1);
        rs0 += __shfl_xor_sync(0xffffffffu, rs0, 2);
        rs1 += __shfl_xor_sync(0xffffffffu, rs1, 1);
        rs1 += __shfl_xor_sync(0xffffffffu, rs1, 2);
        l0 = l0 * a0 + rs0;
        l1 = l1 * a1 + rs1;
#pragma unroll
        for (int d = 0; d < 16; d++) {
            O[d][0] *= a0; O[d][1] *= a0;
            O[d][2] *= a1; O[d][3] *= a1;
        }

        uint32_t phi[4][4], plo[4][4];
#pragma unroll
        for (int kf2 = 0; kf2 < 4; kf2++) {
            split2(s[2 * kf2][0],     s[2 * kf2][1],     phi[kf2][0], plo[kf2][0]);
            split2(s[2 * kf2][2],     s[2 * kf2][3],     phi[kf2][1], plo[kf2][1]);
            split2(s[2 * kf2 + 1][0], s[2 * kf2 + 1][1], phi[kf2][2], plo[kf2][2]);
            split2(s[2 * kf2 + 1][2], s[2 * kf2 + 1][3], phi[kf2][3], plo[kf2][3]);
        }

#pragma unroll
        for (int d = 0; d < 16; d++) {
#pragma unroll
            for (int kf2 = 0; kf2 < 4; kf2++) {
                uint32_t addr = sbase + (uint32_t)((kf2 * 16 + (lane & 15)) * V_ROW + d * 16);
                uint32_t bh[2], bl[2];
                ldsm_x2_t(bh, addr + A_VHI);
                ldsm_x2_t(bl, addr + A_VLO);
                mma_bf16(O[d], phi[kf2], bh);
                mma_bf16(O[d], phi[kf2], bl);
                mma_bf16(O[d], plo[kf2], bh);
            }
        }
    }

    float i0 = 1.f / l0, i1 = 1.f / l1;
    int r0 = qb * 128 + w * 16 + (lane >> 2);
#pragma unroll
    for (int d = 0; d < 16; d++) {
        int col = d * 8 + (lane & 3) * 2;
        *(float2*)&o[((size_t)qh * L_SEQ + r0) * 128 + col] =
            make_float2(O[d][0] * i0, O[d][1] * i0);
        *(float2*)&o[((size_t)qh * L_SEQ + r0 + 8) * 128 + col] =
            make_float2(O[d][2] * i1, O[d][3] * i1);
    }
}

// ---------------------------------------------------------------------------
// RoPE: table build + bandwidth-only apply
// ---------------------------------------------------------------------------
__global__ void rope_table_kernel()
{
    int i = blockIdx.x * 256 + threadIdx.x;       // 0 .. 131071
    int l = i >> 6, d = i & 63;
    float inv_freq = exp2f(-(float)d * (13.287712379549449f / 64.f));
    float s, c;
    sincosf((float)l * inv_freq, &s, &c);
    g_ropecs[i * 2]     = c;
    g_ropecs[i * 2 + 1] = s;
}

__global__ void rope_kernel(float* __restrict__ buf, int stride)
{
    const int l = blockIdx.x;
    const int h = blockIdx.y;
    const int d = threadIdx.x;

    float2 cs = *(const float2*)&g_ropecs[(l * 64 + d) * 2];

    float* p = buf + (size_t)l * stride + h * DHEAD;
    float x1 = p[d];
    float x2 = p[d + 64];
    p[d]      = x1 * cs.x - x2 * cs.y;
    p[d + 64] = x2 * cs.x + x1 * cs.y;
}

// ---------------------------------------------------------------------------
// lam = sigmoid(x @ W_lam + b_lam)
// ---------------------------------------------------------------------------
__global__ void lam_kernel(const float* __restrict__ x,
                           const float* __restrict__ Wl,
                           const float* __restrict__ bl,
                           float* __restrict__ lam)
{
    __shared__ float part[256];
    const int l = blockIdx.x;
    const int t = threadIdx.x;
    const int h = t & 15;
    const int p = t >> 4;

    float s = 0.f;
#pragma unroll 4
    for (int j = 0; j < 128; j++) {
        int kk = p * 128 + j;
        s += x[(size_t)l * D_MODEL + kk] * Wl[(size_t)kk * NHEADS + h];
    }
    part[t] = s;
    __syncthreads();
    if (t < NHEADS) {
        float tot = bl[t];
#pragma unroll
        for (int p2 = 0; p2 < 16; p2++) tot += part[p2 * 16 + t];
        lam[(size_t)l * NHEADS + t] = 1.f / (1.f + __expf(-tot));
    }
}

// ---------------------------------------------------------------------------
// combine: emits bf16 hi/lo bit patterns directly for the Wout GEMM
// ---------------------------------------------------------------------------
__global__ void combine_kernel2(const float* __restrict__ attn,
                                const float* __restrict__ lam,
                                uint16_t* __restrict__ hi, uint16_t* __restrict__ lo)
{
    int idx = blockIdx.x * 256 + threadIdx.x;     // over L*1024 pairs
    int l  = idx >> 10;
    int cp = idx & 1023;
    int h  = cp >> 6;
    int dp = (cp & 63) * 2;
    float a1a = attn[((size_t)(2 * h)     * L_SEQ + l) * DHEAD + dp];
    float a1b = attn[((size_t)(2 * h)     * L_SEQ + l) * DHEAD + dp + 1];
    float a2a = attn[((size_t)(2 * h + 1) * L_SEQ + l) * DHEAD + dp];
    float a2b = attn[((size_t)(2 * h + 1) * L_SEQ + l) * DHEAD + dp + 1];
    float lm  = lam[(size_t)l * NHEADS + h];
    uint32_t hw, lw;
    split2(a1a - lm * a2a, a1b - lm * a2b, hw, lw);
    ((uint32_t*)hi)[idx] = hw;
    ((uint32_t*)lo)[idx] = lw;
}

// ---------------------------------------------------------------------------
// kernel_launch
// inputs: 0=x 1=W_DKV 2=W_UK 3=W_UV 4=W_DQ 5=W_UQ 6=W_lam 7=b_lam 8=W_out
// ---------------------------------------------------------------------------
extern "C" void kernel_launch(void* const* d_in, const int* in_sizes, int n_in,
                              void* d_out, int out_size)
{
    const float* x     = (const float*)d_in[0];
    const float* W_DKV = (const float*)d_in[1];
    const float* W_UK  = (const float*)d_in[2];
    const float* W_UV  = (const float*)d_in[3];
    const float* W_DQ  = (const float*)d_in[4];
    const float* W_UQ  = (const float*)d_in[5];
    const float* W_lam = (const float*)d_in[6];
    const float* b_lam = (const float*)d_in[7];
    const float* W_out = (const float*)d_in[8];
    float* out = (float*)d_out;

    float *kbuf, *qbuf, *attn, *lam;
    cudaGetSymbolAddress((void**)&kbuf, g_k);
    cudaGetSymbolAddress((void**)&qbuf, g_q);
    cudaGetSymbolAddress((void**)&attn, g_attn);
    cudaGetSymbolAddress((void**)&lam,  g_lam);

    uint16_t *xh,*xl,*wdkvh,*wdkvl,*wukh,*wukl,*wuvh,*wuvl,*wdqh,*wdql,
             *wuqh,*wuql,*wouth,*woutl,*ckvh,*ckvl,*cqh,*cql,*vh,*vl,
             *kth,*ktl,*cmbh,*cmbl;
    cudaGetSymbolAddress((void**)&xh,    g_xhi);   cudaGetSymbolAddress((void**)&xl,    g_xlo);
    cudaGetSymbolAddress((void**)&wdkvh, g_wdkvh); cudaGetSymbolAddress((void**)&wdkvl, g_wdkvl);
    cudaGetSymbolAddress((void**)&wukh,  g_wukh);  cudaGetSymbolAddress((void**)&wukl,  g_wukl);
    cudaGetSymbolAddress((void**)&wuvh,  g_wuvh);  cudaGetSymbolAddress((void**)&wuvl,  g_wuvl);
    cudaGetSymbolAddress((void**)&wdqh,  g_wdqh);  cudaGetSymbolAddress((void**)&wdql,  g_wdql);
    cudaGetSymbolAddress((void**)&wuqh,  g_wuqh);  cudaGetSymbolAddress((void**)&wuql,  g_wuql);
    cudaGetSymbolAddress((void**)&wouth, g_wouth); cudaGetSymbolAddress((void**)&woutl, g_woutl);
    cudaGetSymbolAddress((void**)&ckvh,  g_ckvh);  cudaGetSymbolAddress((void**)&ckvl,  g_ckvl);
    cudaGetSymbolAddress((void**)&cqh,   g_cqh);   cudaGetSymbolAddress((void**)&cql,   g_cql);
    cudaGetSymbolAddress((void**)&vh,    g_vh);    cudaGetSymbolAddress((void**)&vl,    g_vl);
    cudaGetSymbolAddress((void**)&kth,   g_kth);   cudaGetSymbolAddress((void**)&ktl,   g_ktl);
    cudaGetSymbolAddress((void**)&cmbh,  g_cmbh);  cudaGetSymbolAddress((void**)&cmbl,  g_cmbl);

    cudaFuncSetAttribute(attn_tc3, cudaFuncAttributeMaxDynamicSharedMemorySize, ATT_SMEM);

    // rope table + pre-split inputs (elementwise)
    rope_table_kernel<<<512, 256>>>();
    split_kernel<<<(L_SEQ * D_MODEL) / 1024, 256>>>(x,     xh,    xl);
    split_kernel<<<(D_MODEL * DC) / 1024,    256>>>(W_DKV, wdkvh, wdkvl);
    split_kernel<<<(DC * D_MODEL) / 1024,    256>>>(W_UK,  wukh,  wukl);
    split_kernel<<<(DC * D_MODEL) / 1024,    256>>>(W_UV,  wuvh,  wuvl);
    split_kernel<<<(D_MODEL * DCQ) / 1024,   256>>>(W_DQ,  wdqh,  wdql);
    split_kernel<<<(DCQ * 2 * D_MODEL)/1024, 256>>>(W_UQ,  wuqh,  wuql);
    split_kernel<<<(D_MODEL * D_MODEL)/1024, 256>>>(W_out, wouth, woutl);

    GemmJob Z = {}; Z.nx = 0;

    // launch 1: DKV || DQ  (both read x, K=2048): 12 x-tiles x 16 = 192 CTAs
    {
        GemmJob jd = { xh, xl, wdkvh, wdkvl, nullptr, ckvh, ckvl, D_MODEL, DC,  4, 1 };
        GemmJob jq = { xh, xl, wdqh,  wdql,  nullptr, cqh,  cql,  D_MODEL, DCQ, 8, 1 };
        tc_gemm_multi<<<dim3(12, 16), 256>>>(jd, jq, Z);
    }

    // launch 2: UQ || UK || UV fused (all ready after launch 1): 64 x 16 = 1024 CTAs
    // heavy job (UQ, 32 iters) first for work-stealing balance
    {
        GemmJob juq = { cqh,  cql,  wuqh, wuql, qbuf,    nullptr, nullptr, DCQ, 2 * D_MODEL, 32, 0 };
        GemmJob juk = { ckvh, ckvl, wukh, wukl, kbuf,    nullptr, nullptr, DC,  D_MODEL,     16, 0 };
        GemmJob juv = { ckvh, ckvl, wuvh, wuvl, nullptr, vh,      vl,      DC,  D_MODEL,     16, 1 };
        tc_gemm_multi<<<dim3(64, 16), 256>>>(juq, juk, juv);
    }

    // RoPE (table-driven)
    rope_kernel<<<dim3(L_SEQ, QHEADS), 64>>>(qbuf, 2 * D_MODEL);
    rope_kernel<<<dim3(L_SEQ, NHEADS), 64>>>(kbuf, D_MODEL);

    // K -> transposed hi/lo
    ktrans_split<<<dim3(L_SEQ / 32, 4, NHEADS), dim3(32, 8)>>>(kbuf, kth, ktl);

    // gate
    lam_kernel<<<L_SEQ, 256>>>(x, W_lam, b_lam, lam);

    // attention (heavy-first ordering)
    attn_tc3<<<dim3(L_SEQ / 128, QHEADS), 256, ATT_SMEM>>>(qbuf, kth, ktl, vh, vl, attn);

    // differential combine -> bf16 hi/lo
    combine_kernel2<<<(L_SEQ * D_MODEL / 2) / 256, 256>>>(attn, lam, cmbh, cmbl);

    // output projection
    {
        GemmJob jo = { cmbh, cmbl, wouth, woutl, out, nullptr, nullptr, D_MODEL, D_MODEL, 16, 0 };
        tc_gemm_multi<<<dim3(16, 16), 256>>>(jo, Z, Z);
    }
}

// round 17
// speedup vs baseline: 1.2257x; 1.0444x over previous
#include <cuda_runtime.h>
#include <cuda_bf16.h>
#include <math.h>
#include <stdint.h>

#define L_SEQ   2048
#define D_MODEL 2048
#define NHEADS  16
#define DHEAD   128
#define DC      512
#define DCQ     1024
#define QHEADS  32

// ---------------------------------------------------------------------------
// Scratch (static device globals -- POD types only; __nv_bfloat16 globals
// break the build (confirmed R8 vs R9))
// ---------------------------------------------------------------------------
__device__ float g_k   [L_SEQ * D_MODEL];
__device__ float g_q   [L_SEQ * 2 * D_MODEL];
__device__ float g_attn[QHEADS * L_SEQ * DHEAD];
__device__ float g_lam [L_SEQ * NHEADS];
__device__ float g_ropecs[L_SEQ * 64 * 2];   // cos/sin table

__device__ unsigned short g_xhi [L_SEQ * D_MODEL],    g_xlo [L_SEQ * D_MODEL];
__device__ unsigned short g_wdkvh[D_MODEL * DC],      g_wdkvl[D_MODEL * DC];
__device__ unsigned short g_wukh [DC * D_MODEL],      g_wukl [DC * D_MODEL];
__device__ unsigned short g_wuvh [DC * D_MODEL],      g_wuvl [DC * D_MODEL];
__device__ unsigned short g_wdqh [D_MODEL * DCQ],     g_wdql [D_MODEL * DCQ];
__device__ unsigned short g_wuqh [DCQ * 2 * D_MODEL], g_wuql [DCQ * 2 * D_MODEL];
__device__ unsigned short g_wouth[D_MODEL * D_MODEL], g_woutl[D_MODEL * D_MODEL];
__device__ unsigned short g_ckvh [L_SEQ * DC],        g_ckvl [L_SEQ * DC];
__device__ unsigned short g_cqh  [L_SEQ * DCQ],       g_cql  [L_SEQ * DCQ];
__device__ unsigned short g_vh   [L_SEQ * D_MODEL],   g_vl   [L_SEQ * D_MODEL];
__device__ unsigned short g_kth  [D_MODEL * L_SEQ],   g_ktl  [D_MODEL * L_SEQ];
__device__ unsigned short g_cmbh [L_SEQ * D_MODEL],   g_cmbl [L_SEQ * D_MODEL];

// ---------------------------------------------------------------------------
// Helpers (sm_80-baseline features only)
// ---------------------------------------------------------------------------
__device__ __forceinline__ uint32_t smem_u32(const void* p) {
    uint32_t r;
    asm("{ .reg .u64 t; cvta.to.shared.u64 t, %1; cvt.u32.u64 %0, t; }"
        : "=r"(r) : "l"(p));
    return r;
}
__device__ __forceinline__ void split_bf(float v, uint16_t& h, uint16_t& l) {
    __nv_bfloat16 hb = __float2bfloat16_rn(v);
    float hf = __bfloat162float(hb);
    __nv_bfloat16 lb = __float2bfloat16_rn(v - hf);
    h = *(uint16_t*)&hb;
    l = *(uint16_t*)&lb;
}
__device__ __forceinline__ void split2(float a, float b, uint32_t& hp, uint32_t& lp) {
    uint16_t ha, la, hb, lb;
    split_bf(a, ha, la);
    split_bf(b, hb, lb);
    hp = (uint32_t)ha | ((uint32_t)hb << 16);
    lp = (uint32_t)la | ((uint32_t)lb << 16);
}
__device__ __forceinline__ void ldsm_x4(uint32_t* r, uint32_t addr) {
    asm volatile("ldmatrix.sync.aligned.m8n8.x4.shared.b16 {%0,%1,%2,%3}, [%4];"
                 : "=r"(r[0]), "=r"(r[1]), "=r"(r[2]), "=r"(r[3]) : "r"(addr));
}
__device__ __forceinline__ void ldsm_x2_t(uint32_t* r, uint32_t addr) {
    asm volatile("ldmatrix.sync.aligned.m8n8.x2.trans.shared.b16 {%0,%1}, [%2];"
                 : "=r"(r[0]), "=r"(r[1]) : "r"(addr));
}
__device__ __forceinline__ void mma_bf16(float* d, const uint32_t* a, const uint32_t* b) {
    asm volatile(
        "mma.sync.aligned.m16n8k16.row.col.f32.bf16.bf16.f32 "
        "{%0,%1,%2,%3}, {%4,%5,%6,%7}, {%8,%9}, {%0,%1,%2,%3};"
        : "+f"(d[0]), "+f"(d[1]), "+f"(d[2]), "+f"(d[3])
        : "r"(a[0]), "r"(a[1]), "r"(a[2]), "r"(a[3]), "r"(b[0]), "r"(b[1]));
}

// ---------------------------------------------------------------------------
// mega_split: ALL 7 fp32 -> bf16 hi/lo conversions in one launch.
// blockIdx.x ranges route to jobs (uniform per block).
// Block counts (256 thr, 4 float4/thr... actually 1 float4/thr):
//   x:4096  DKV:1024  UK:1024  UV:1024  DQ:2048  UQ:4096  Wout:4096
// ---------------------------------------------------------------------------
__global__ void mega_split(
    const float* s0, uint16_t* h0, uint16_t* l0_,
    const float* s1, uint16_t* h1, uint16_t* l1_,
    const float* s2, uint16_t* h2, uint16_t* l2_,
    const float* s3, uint16_t* h3, uint16_t* l3_,
    const float* s4, uint16_t* h4, uint16_t* l4_,
    const float* s5, uint16_t* h5, uint16_t* l5_,
    const float* s6, uint16_t* h6, uint16_t* l6_)
{
    int b = blockIdx.x;
    const float* src; uint16_t* hi; uint16_t* lo;
    if      (b < 4096)  { src = s0; hi = h0; lo = l0_; }
    else if (b < 5120)  { src = s1; hi = h1; lo = l1_; b -= 4096; }
    else if (b < 6144)  { src = s2; hi = h2; lo = l2_; b -= 5120; }
    else if (b < 7168)  { src = s3; hi = h3; lo = l3_; b -= 6144; }
    else if (b < 9216)  { src = s4; hi = h4; lo = l4_; b -= 7168; }
    else if (b < 13312) { src = s5; hi = h5; lo = l5_; b -= 9216; }
    else                { src = s6; hi = h6; lo = l6_; b -= 13312; }

    int i = b * 256 + threadIdx.x;       // float4 index
    float4 v = ((const float4*)src)[i];
    uint32_t ha, la, hb, lb;
    split2(v.x, v.y, ha, la);
    split2(v.z, v.w, hb, lb);
    ((uint2*)hi)[i] = make_uint2(ha, hb);
    ((uint2*)lo)[i] = make_uint2(la, lb);
}

// ---------------------------------------------------------------------------
// ktrans_rope: k fp32 [L][2048] -> RoPE -> kT hi/lo [16][128][L]
// grid (L/32, 2, 16), block (32,8). blockIdx.y selects d0 in {0,32};
// each block handles d-pair columns (d0..d0+31) and (d0+64..d0+95).
// ---------------------------------------------------------------------------
__global__ void ktrans_rope(const float* __restrict__ k,
                            uint16_t* __restrict__ kth, uint16_t* __restrict__ ktl)
{
    __shared__ float ta[32][33];
    __shared__ float tb[32][33];
    const int l0 = blockIdx.x * 32;
    const int d0 = blockIdx.y * 32;     // 0 or 32
    const int h  = blockIdx.z;
    const int tx = threadIdx.x;
    const int ty = threadIdx.y;

#pragma unroll
    for (int i = 0; i < 4; i++) {
        int lr = ty + i * 8;
        const float* row = k + (size_t)(l0 + lr) * D_MODEL + h * DHEAD;
        ta[lr][tx] = row[d0 + tx];
        tb[lr][tx] = row[d0 + 64 + tx];
    }
    __syncthreads();
#pragma unroll
    for (int i = 0; i < 4; i++) {
        int dr = ty + i * 8;            // 0..31 within block -> d = d0+dr
        float x1 = ta[tx][dr];
        float x2 = tb[tx][dr];
        float2 cs = *(const float2*)&g_ropecs[((l0 + tx) * 64 + d0 + dr) * 2];
        float o1 = x1 * cs.x - x2 * cs.y;
        float o2 = x2 * cs.x + x1 * cs.y;
        uint16_t hh, ll;
        split_bf(o1, hh, ll);
        size_t offA = (size_t)(h * DHEAD + d0 + dr) * L_SEQ + l0 + tx;
        kth[offA] = hh;  ktl[offA] = ll;
        split_bf(o2, hh, ll);
        size_t offB = (size_t)(h * DHEAD + d0 + dr + 64) * L_SEQ + l0 + tx;
        kth[offB] = hh;  ktl[offB] = ll;
    }
}

// ---------------------------------------------------------------------------
// rope_q: in-place RoPE on q [L][4096]; 256-thread blocks, cos/sin loaded
// once per thread and reused across all 32 heads (angle is head-invariant).
// ---------------------------------------------------------------------------
__global__ void rope_q(float* __restrict__ buf)
{
    const int l  = blockIdx.x;
    const int t  = threadIdx.x;
    const int d  = t & 63;
    const int h0 = t >> 6;              // 0..3

    float2 cs = *(const float2*)&g_ropecs[(l * 64 + d) * 2];
    float* base = buf + (size_t)l * 4096;
#pragma unroll
    for (int i = 0; i < 8; i++) {
        float* p = base + (h0 + i * 4) * DHEAD;
        float x1 = p[d];
        float x2 = p[d + 64];
        p[d]      = x1 * cs.x - x2 * cs.y;
        p[d + 64] = x2 * cs.x + x1 * cs.y;
    }
}

// ---------------------------------------------------------------------------
// TC GEMM multi-job (R15, unchanged)
// ---------------------------------------------------------------------------
struct GemmJob {
    const uint16_t *Ah, *Al, *Bh, *Bl;
    float* Cf;
    uint16_t *Ch, *Cl;
    int K, N, nx, mode;
};

#define GA_ROW 80
#define GB_ROW 272
#define G_AHI  0
#define G_ALO  (128 * GA_ROW)
#define G_BHI  (2 * 128 * GA_ROW)
#define G_BLO  (G_BHI + 32 * GB_ROW)
#define G_TOT  (G_BLO + 32 * GB_ROW)     // 37888

__global__ __launch_bounds__(256, 2)
void tc_gemm_multi(GemmJob j0, GemmJob j1, GemmJob j2)
{
    __shared__ __align__(16) char sm[G_TOT];
    const int tid  = threadIdx.x;
    const int wid  = tid >> 5;
    const int lane = tid & 31;
    const int wr   = wid >> 2;
    const int wc   = wid & 3;
    const int brow = blockIdx.y * 128;

    GemmJob j;
    int bx = blockIdx.x;
    if (bx < j0.nx)                { j = j0; }
    else if (bx < j0.nx + j1.nx)   { j = j1; bx -= j0.nx; }
    else                           { j = j2; bx -= j0.nx + j1.nx; }
    const int bcol = bx * 128;
    const int K = j.K, N = j.N;

    const uint32_t sbase = smem_u32(sm);

    float acc[4][4][4];
#pragma unroll
    for (int i = 0; i < 4; i++)
#pragma unroll
        for (int jj = 0; jj < 4; jj++)
#pragma unroll
            for (int t = 0; t < 4; t++) acc[i][jj][t] = 0.f;

    const uint32_t a_lane_off = (uint32_t)((lane & 15) * GA_ROW + ((lane >> 4) << 3) * 2);
    const uint32_t b_lane_off = (uint32_t)((lane & 15) * GB_ROW);

    const int nIter = K >> 5;
    for (int it = 0; it < nIter; it++) {
        const int k0 = it << 5;
#pragma unroll
        for (int c = 0; c < 8; c++) {
            int id = c * 256 + tid;
            if (c < 2) {
                int row = id >> 2, c16 = id & 3;
                uint4 v = *(const uint4*)(j.Ah + (size_t)(brow + row) * K + k0 + c16 * 8);
                *(uint4*)(sm + G_AHI + row * GA_ROW + c16 * 16) = v;
            } else if (c < 4) {
                int jx = id - 512;
                int row = jx >> 2, c16 = jx & 3;
                uint4 v = *(const uint4*)(j.Al + (size_t)(brow + row) * K + k0 + c16 * 8);
                *(uint4*)(sm + G_ALO + row * GA_ROW + c16 * 16) = v;
            } else if (c < 6) {
                int jx = id - 1024;
                int kk = jx >> 4, c16 = jx & 15;
                uint4 v = *(const uint4*)(j.Bh + (size_t)(k0 + kk) * N + bcol + c16 * 8);
                *(uint4*)(sm + G_BHI + kk * GB_ROW + c16 * 16) = v;
            } else {
                int jx = id - 1536;
                int kk = jx >> 4, c16 = jx & 15;
                uint4 v = *(const uint4*)(j.Bl + (size_t)(k0 + kk) * N + bcol + c16 * 8);
                *(uint4*)(sm + G_BLO + kk * GB_ROW + c16 * 16) = v;
            }
        }
        __syncthreads();

#pragma unroll
        for (int ks = 0; ks < 2; ks++) {
            const uint32_t kb16 = (uint32_t)(ks * 16);
            uint32_t bhiF[4][2], bloF[4][2];
#pragma unroll
            for (int fn = 0; fn < 4; fn++) {
                uint32_t nb = (uint32_t)((wc * 32 + fn * 8) * 2);
                uint32_t ba = sbase + kb16 * GB_ROW + b_lane_off + nb;
                ldsm_x2_t(bhiF[fn], ba + G_BHI);
                ldsm_x2_t(bloF[fn], ba + G_BLO);
            }
#pragma unroll
            for (int fm = 0; fm < 4; fm++) {
                uint32_t row0 = (uint32_t)(wr * 64 + fm * 16);
                uint32_t aa = sbase + row0 * GA_ROW + kb16 * 2 + a_lane_off;
                uint32_t ahiF[4], aloF[4];
                ldsm_x4(ahiF, aa + G_AHI);
                ldsm_x4(aloF, aa + G_ALO);
#pragma unroll
                for (int fn = 0; fn < 4; fn++) {
                    mma_bf16(acc[fm][fn], ahiF, bhiF[fn]);
                    mma_bf16(acc[fm][fn], ahiF, bloF[fn]);
                    mma_bf16(acc[fm][fn], aloF, bhiF[fn]);
                }
            }
        }
        __syncthreads();
    }

    if (j.mode == 0) {
#pragma unroll
        for (int fm = 0; fm < 4; fm++)
#pragma unroll
            for (int fn = 0; fn < 4; fn++) {
                int r0 = brow + wr * 64 + fm * 16 + (lane >> 2);
                int c0 = bcol + wc * 32 + fn * 8 + (lane & 3) * 2;
                *(float2*)&j.Cf[(size_t)r0 * N + c0] =
                    make_float2(acc[fm][fn][0], acc[fm][fn][1]);
                *(float2*)&j.Cf[(size_t)(r0 + 8) * N + c0] =
                    make_float2(acc[fm][fn][2], acc[fm][fn][3]);
            }
    } else {
#pragma unroll
        for (int fm = 0; fm < 4; fm++)
#pragma unroll
            for (int fn = 0; fn < 4; fn++) {
                int r0 = brow + wr * 64 + fm * 16 + (lane >> 2);
                int c0 = bcol + wc * 32 + fn * 8 + (lane & 3) * 2;
                uint32_t h0, l0, h1, l1;
                split2(acc[fm][fn][0], acc[fm][fn][1], h0, l0);
                split2(acc[fm][fn][2], acc[fm][fn][3], h1, l1);
                *(uint32_t*)&j.Ch[(size_t)r0 * N + c0]       = h0;
                *(uint32_t*)&j.Cl[(size_t)r0 * N + c0]       = l0;
                *(uint32_t*)&j.Ch[(size_t)(r0 + 8) * N + c0] = h1;
                *(uint32_t*)&j.Cl[(size_t)(r0 + 8) * N + c0] = l1;
            }
    }
}

// ---------------------------------------------------------------------------
// Tensor-core causal flash attention (R15, unchanged; heavy-first ordering)
// ---------------------------------------------------------------------------
#define KT_ROW   144
#define V_ROW    272
#define A_KTHI   0
#define A_KTLO   (128 * KT_ROW)
#define A_VHI    (2 * 128 * KT_ROW)
#define A_VLO    (A_VHI + 64 * V_ROW)
#define ATT_SMEM (A_VLO + 64 * V_ROW)           // 71680

__global__ __launch_bounds__(256, 1) void attn_tc3(
    const float* __restrict__ q,
    const uint16_t* __restrict__ kth, const uint16_t* __restrict__ ktl,
    const uint16_t* __restrict__ vh,  const uint16_t* __restrict__ vl,
    float* __restrict__ o)
{
    extern __shared__ char sm[];
    const int qb   = gridDim.x - 1 - blockIdx.x;
    const int qh   = blockIdx.y;
    const int kvh  = qh >> 1;
    const int tid  = threadIdx.x;
    const int w    = tid >> 5;
    const int lane = tid & 31;
    const uint32_t sbase = smem_u32(sm);
    const float scale = 0.08838834764831843f;

    uint32_t qhi[8][4], qlo[8][4];
    {
        const int r0 = qb * 128 + w * 16 + (lane >> 2);
        const float* q0 = q + (size_t)r0 * 4096 + qh * 128 + (lane & 3) * 2;
        const float* q1 = q0 + 8 * 4096;
#pragma unroll
        for (int kf = 0; kf < 8; kf++) {
            float2 x0 = *(const float2*)(q0 + kf * 16);
            float2 x1 = *(const float2*)(q1 + kf * 16);
            float2 x2 = *(const float2*)(q0 + kf * 16 + 8);
            float2 x3 = *(const float2*)(q1 + kf * 16 + 8);
            split2(x0.x * scale, x0.y * scale, qhi[kf][0], qlo[kf][0]);
            split2(x1.x * scale, x1.y * scale, qhi[kf][1], qlo[kf][1]);
            split2(x2.x * scale, x2.y * scale, qhi[kf][2], qlo[kf][2]);
            split2(x3.x * scale, x3.y * scale, qhi[kf][3], qlo[kf][3]);
        }
    }

    float m0 = -1e30f, m1 = -1e30f, l0 = 0.f, l1 = 0.f;
    float O[16][4];
#pragma unroll
    for (int d = 0; d < 16; d++)
#pragma unroll
        for (int t = 0; t < 4; t++) O[d][t] = 0.f;

    const int kb_max = 2 * qb + 1;
    for (int kb = 0; kb <= kb_max; kb++) {
        __syncthreads();

#pragma unroll
        for (int c = 0; c < 16; c++) {
            int id = c * 256 + tid;
            if (c < 4) {
                int dh = id >> 3, kc = id & 7;
                uint4 v = *(const uint4*)(kth + (size_t)(kvh * DHEAD + dh) * L_SEQ + kb * 64 + kc * 8);
                *(uint4*)(sm + A_KTHI + dh * KT_ROW + kc * 16) = v;
            } else if (c < 8) {
                int j = id - 1024;
                int dh = j >> 3, kc = j & 7;
                uint4 v = *(const uint4*)(ktl + (size_t)(kvh * DHEAD + dh) * L_SEQ + kb * 64 + kc * 8);
                *(uint4*)(sm + A_KTLO + dh * KT_ROW + kc * 16) = v;
            } else if (c < 12) {
                int j = id - 2048;
                int key = j >> 4, c16 = j & 15;
                uint4 v = *(const uint4*)(vh + (size_t)(kb * 64 + key) * D_MODEL + kvh * DHEAD + c16 * 8);
                *(uint4*)(sm + A_VHI + key * V_ROW + c16 * 16) = v;
            } else {
                int j = id - 3072;
                int key = j >> 4, c16 = j & 15;
                uint4 v = *(const uint4*)(vl + (size_t)(kb * 64 + key) * D_MODEL + kvh * DHEAD + c16 * 8);
                *(uint4*)(sm + A_VLO + key * V_ROW + c16 * 16) = v;
            }
        }
        __syncthreads();

        float s[8][4];
#pragma unroll
        for (int j = 0; j < 8; j++) {
            s[j][0] = s[j][1] = s[j][2] = s[j][3] = 0.f;
#pragma unroll
            for (int kf = 0; kf < 8; kf++) {
                uint32_t addr = sbase + (uint32_t)((kf * 16 + (lane & 15)) * KT_ROW + j * 16);
                uint32_t bh[2], bl[2];
                ldsm_x2_t(bh, addr + A_KTHI);
                ldsm_x2_t(bl, addr + A_KTLO);
                mma_bf16(s[j], qhi[kf], bh);
                mma_bf16(s[j], qhi[kf], bl);
                mma_bf16(s[j], qlo[kf], bh);
            }
        }

        if (kb >= 2 * qb) {
            int row0 = qb * 128 + w * 16 + (lane >> 2);
            int colb = kb * 64 + (lane & 3) * 2;
#pragma unroll
            for (int j = 0; j < 8; j++) {
                int c0 = colb + j * 8;
                if (c0     > row0)     s[j][0] = -1e30f;
                if (c0 + 1 > row0)     s[j][1] = -1e30f;
                if (c0     > row0 + 8) s[j][2] = -1e30f;
                if (c0 + 1 > row0 + 8) s[j][3] = -1e30f;
            }
        }

        float mx0 = -1e30f, mx1 = -1e30f;
#pragma unroll
        for (int j = 0; j < 8; j++) {
            mx0 = fmaxf(mx0, fmaxf(s[j][0], s[j][1]));
            mx1 = fmaxf(mx1, fmaxf(s[j][2], s[j][3]));
        }
        mx0 = fmaxf(mx0, __shfl_xor_sync(0xffffffffu, mx0, 1));
        mx0 = fmaxf(mx0, __shfl_xor_sync(0xffffffffu, mx0, 2));
        mx1 = fmaxf(mx1, __shfl_xor_sync(0xffffffffu, mx1, 1));
        mx1 = fmaxf(mx1, __shfl_xor_sync(0xffffffffu, mx1, 2));
        float mn0 = fmaxf(m0, mx0), mn1 = fmaxf(m1, mx1);
        float a0 = __expf(m0 - mn0), a1 = __expf(m1 - mn1);
        m0 = mn0; m1 = mn1;
        float rs0 = 0.f, rs1 = 0.f;
#pragma unroll
        for (int j = 0; j < 8; j++) {
            s[j][0] = __expf(s[j][0] - mn0);
            s[j][1] = __expf(s[j][1] - mn0);
            s[j][2] = __expf(s[j][2] - mn1);
            s[j][3] = __expf(s[j][3] - mn1);
            rs0 += s[j][0] + s[j][1];
            rs1 += s[j][2] + s[j][3];
        }
        rs0 += __shfl_xor_sync(0xffffffffu, rs0, 1);
        rs0 += __shfl_xor_sync(0xffffffffu, rs0, 2);
        rs1 += __shfl_xor_sync(0xffffffffu, rs1, 1);
        rs1 += __shfl_xor_sync(0xffffffffu, rs1, 2);
        l0 = l0 * a0 + rs0;
        l1 = l1 * a1 + rs1;
#pragma unroll
        for (int d = 0; d < 16; d++) {
            O[d][0] *= a0; O[d][1] *= a0;
            O[d][2] *= a1; O[d][3] *= a1;
        }

        uint32_t phi[4][4], plo[4][4];
#pragma unroll
        for (int kf2 = 0; kf2 < 4; kf2++) {
            split2(s[2 * kf2][0],     s[2 * kf2][1],     phi[kf2][0], plo[kf2][0]);
            split2(s[2 * kf2][2],     s[2 * kf2][3],     phi[kf2][1], plo[kf2][1]);
            split2(s[2 * kf2 + 1][0], s[2 * kf2 + 1][1], phi[kf2][2], plo[kf2][2]);
            split2(s[2 * kf2 + 1][2], s[2 * kf2 + 1][3], phi[kf2][3], plo[kf2][3]);
        }

#pragma unroll
        for (int d = 0; d < 16; d++) {
#pragma unroll
            for (int kf2 = 0; kf2 < 4; kf2++) {
                uint32_t addr = sbase + (uint32_t)((kf2 * 16 + (lane & 15)) * V_ROW + d * 16);
                uint32_t bh[2], bl[2];
                ldsm_x2_t(bh, addr + A_VHI);
                ldsm_x2_t(bl, addr + A_VLO);
                mma_bf16(O[d], phi[kf2], bh);
                mma_bf16(O[d], phi[kf2], bl);
                mma_bf16(O[d], plo[kf2], bh);
            }
        }
    }

    float i0 = 1.f / l0, i1 = 1.f / l1;
    int r0 = qb * 128 + w * 16 + (lane >> 2);
#pragma unroll
    for (int d = 0; d < 16; d++) {
        int col = d * 8 + (lane & 3) * 2;
        *(float2*)&o[((size_t)qh * L_SEQ + r0) * 128 + col] =
            make_float2(O[d][0] * i0, O[d][1] * i0);
        *(float2*)&o[((size_t)qh * L_SEQ + r0 + 8) * 128 + col] =
            make_float2(O[d][2] * i1, O[d][3] * i1);
    }
}

// ---------------------------------------------------------------------------
// RoPE table build
// ---------------------------------------------------------------------------
__global__ void rope_table_kernel()
{
    int i = blockIdx.x * 256 + threadIdx.x;       // 0 .. 131071
    int l = i >> 6, d = i & 63;
    float inv_freq = exp2f(-(float)d * (13.287712379549449f / 64.f));
    float s, c;
    sincosf((float)l * inv_freq, &s, &c);
    g_ropecs[i * 2]     = c;
    g_ropecs[i * 2 + 1] = s;
}

// ---------------------------------------------------------------------------
// lam = sigmoid(x @ W_lam + b_lam)
// ---------------------------------------------------------------------------
__global__ void lam_kernel(const float* __restrict__ x,
                           const float* __restrict__ Wl,
                           const float* __restrict__ bl,
                           float* __restrict__ lam)
{
    __shared__ float part[256];
    const int l = blockIdx.x;
    const int t = threadIdx.x;
    const int h = t & 15;
    const int p = t >> 4;

    float s = 0.f;
#pragma unroll 4
    for (int j = 0; j < 128; j++) {
        int kk = p * 128 + j;
        s += x[(size_t)l * D_MODEL + kk] * Wl[(size_t)kk * NHEADS + h];
    }
    part[t] = s;
    __syncthreads();
    if (t < NHEADS) {
        float tot = bl[t];
#pragma unroll
        for (int p2 = 0; p2 < 16; p2++) tot += part[p2 * 16 + t];
        lam[(size_t)l * NHEADS + t] = 1.f / (1.f + __expf(-tot));
    }
}

// ---------------------------------------------------------------------------
// combine: emits bf16 hi/lo bit patterns directly for the Wout GEMM
// ---------------------------------------------------------------------------
__global__ void combine_kernel2(const float* __restrict__ attn,
                                const float* __restrict__ lam,
                                uint16_t* __restrict__ hi, uint16_t* __restrict__ lo)
{
    int idx = blockIdx.x * 256 + threadIdx.x;     // over L*1024 pairs
    int l  = idx >> 10;
    int cp = idx & 1023;
    int h  = cp >> 6;
    int dp = (cp & 63) * 2;
    float a1a = attn[((size_t)(2 * h)     * L_SEQ + l) * DHEAD + dp];
    float a1b = attn[((size_t)(2 * h)     * L_SEQ + l) * DHEAD + dp + 1];
    float a2a = attn[((size_t)(2 * h + 1) * L_SEQ + l) * DHEAD + dp];
    float a2b = attn[((size_t)(2 * h + 1) * L_SEQ + l) * DHEAD + dp + 1];
    float lm  = lam[(size_t)l * NHEADS + h];
    uint32_t hw, lw;
    split2(a1a - lm * a2a, a1b - lm * a2b, hw, lw);
    ((uint32_t*)hi)[idx] = hw;
    ((uint32_t*)lo)[idx] = lw;
}

// ---------------------------------------------------------------------------
// kernel_launch
// inputs: 0=x 1=W_DKV 2=W_UK 3=W_UV 4=W_DQ 5=W_UQ 6=W_lam 7=b_lam 8=W_out
// ---------------------------------------------------------------------------
extern "C" void kernel_launch(void* const* d_in, const int* in_sizes, int n_in,
                              void* d_out, int out_size)
{
    const float* x     = (const float*)d_in[0];
    const float* W_DKV = (const float*)d_in[1];
    const float* W_UK  = (const float*)d_in[2];
    const float* W_UV  = (const float*)d_in[3];
    const float* W_DQ  = (const float*)d_in[4];
    const float* W_UQ  = (const float*)d_in[5];
    const float* W_lam = (const float*)d_in[6];
    const float* b_lam = (const float*)d_in[7];
    const float* W_out = (const float*)d_in[8];
    float* out = (float*)d_out;

    float *kbuf, *qbuf, *attn, *lam;
    cudaGetSymbolAddress((void**)&kbuf, g_k);
    cudaGetSymbolAddress((void**)&qbuf, g_q);
    cudaGetSymbolAddress((void**)&attn, g_attn);
    cudaGetSymbolAddress((void**)&lam,  g_lam);

    uint16_t *xh,*xl,*wdkvh,*wdkvl,*wukh,*wukl,*wuvh,*wuvl,*wdqh,*wdql,
             *wuqh,*wuql,*wouth,*woutl,*ckvh,*ckvl,*cqh,*cql,*vh,*vl,
             *kth,*ktl,*cmbh,*cmbl;
    cudaGetSymbolAddress((void**)&xh,    g_xhi);   cudaGetSymbolAddress((void**)&xl,    g_xlo);
    cudaGetSymbolAddress((void**)&wdkvh, g_wdkvh); cudaGetSymbolAddress((void**)&wdkvl, g_wdkvl);
    cudaGetSymbolAddress((void**)&wukh,  g_wukh);  cudaGetSymbolAddress((void**)&wukl,  g_wukl);
    cudaGetSymbolAddress((void**)&wuvh,  g_wuvh);  cudaGetSymbolAddress((void**)&wuvl,  g_wuvl);
    cudaGetSymbolAddress((void**)&wdqh,  g_wdqh);  cudaGetSymbolAddress((void**)&wdql,  g_wdql);
    cudaGetSymbolAddress((void**)&wuqh,  g_wuqh);  cudaGetSymbolAddress((void**)&wuql,  g_wuql);
    cudaGetSymbolAddress((void**)&wouth, g_wouth); cudaGetSymbolAddress((void**)&woutl, g_woutl);
    cudaGetSymbolAddress((void**)&ckvh,  g_ckvh);  cudaGetSymbolAddress((void**)&ckvl,  g_ckvl);
    cudaGetSymbolAddress((void**)&cqh,   g_cqh);   cudaGetSymbolAddress((void**)&cql,   g_cql);
    cudaGetSymbolAddress((void**)&vh,    g_vh);    cudaGetSymbolAddress((void**)&vl,    g_vl);
    cudaGetSymbolAddress((void**)&kth,   g_kth);   cudaGetSymbolAddress((void**)&ktl,   g_ktl);
    cudaGetSymbolAddress((void**)&cmbh,  g_cmbh);  cudaGetSymbolAddress((void**)&cmbl,  g_cmbl);

    cudaFuncSetAttribute(attn_tc3, cudaFuncAttributeMaxDynamicSharedMemorySize, ATT_SMEM);

    // table + ALL splits in two launches
    rope_table_kernel<<<512, 256>>>();
    mega_split<<<17408, 256>>>(
        x,     xh,    xl,
        W_DKV, wdkvh, wdkvl,
        W_UK,  wukh,  wukl,
        W_UV,  wuvh,  wuvl,
        W_DQ,  wdqh,  wdql,
        W_UQ,  wuqh,  wuql,
        W_out, wouth, woutl);

    GemmJob Z = {}; Z.nx = 0;

    // launch 1: DKV || DQ (both read x, K=2048): 12 x 16 = 192 CTAs
    {
        GemmJob jd = { xh, xl, wdkvh, wdkvl, nullptr, ckvh, ckvl, D_MODEL, DC,  4, 1 };
        GemmJob jq = { xh, xl, wdqh,  wdql,  nullptr, cqh,  cql,  D_MODEL, DCQ, 8, 1 };
        tc_gemm_multi<<<dim3(12, 16), 256>>>(jd, jq, Z);
    }

    // launch 2: UQ || UK || UV fused: 64 x 16 = 1024 CTAs (heavy UQ first)
    {
        GemmJob juq = { cqh,  cql,  wuqh, wuql, qbuf,    nullptr, nullptr, DCQ, 2 * D_MODEL, 32, 0 };
        GemmJob juk = { ckvh, ckvl, wukh, wukl, kbuf,    nullptr, nullptr, DC,  D_MODEL,     16, 0 };
        GemmJob juv = { ckvh, ckvl, wuvh, wuvl, nullptr, vh,      vl,      DC,  D_MODEL,     16, 1 };
        tc_gemm_multi<<<dim3(64, 16), 256>>>(juq, juk, juv);
    }

    // RoPE on Q (table-driven, head-invariant cs reuse)
    rope_q<<<L_SEQ, 256>>>(qbuf);

    // K: RoPE + transpose + split fused
    ktrans_rope<<<dim3(L_SEQ / 32, 2, NHEADS), dim3(32, 8)>>>(kbuf, kth, ktl);

    // gate
    lam_kernel<<<L_SEQ, 256>>>(x, W_lam, b_lam, lam);

    // attention (heavy-first ordering)
    attn_tc3<<<dim3(L_SEQ / 128, QHEADS), 256, ATT_SMEM>>>(qbuf, kth, ktl, vh, vl, attn);

    // differential combine -> bf16 hi/lo
    combine_kernel2<<<(L_SEQ * D_MODEL / 2) / 256, 256>>>(attn, lam, cmbh, cmbl);

    // output projection
    {
        GemmJob jo = { cmbh, cmbl, wouth, woutl, out, nullptr, nullptr, D_MODEL, D_MODEL, 16, 0 };
        tc_gemm_multi<<<dim3(16, 16), 256>>>(jo, Z, Z);
    }
}